// round 9
// baseline (speedup 1.0000x reference)
#include <cuda_runtime.h>
#include <cuda_bf16.h>
#include <cstdint>

// Problem constants
#define SLEN   2048
#define BSZ    8
#define IN_DIM 1024
#define NH     16
#define DH     64
#define NROWS  (SLEN*BSZ)              // 16384
#define NOUT   (NH*(3*DH+1))           // 3088
#define NOUT_PAD 3200

// ---------------- device scratch ----------------
__device__ __nv_bfloat16 g_h_hi[(size_t)NROWS * IN_DIM];
__device__ __nv_bfloat16 g_h_lo[(size_t)NROWS * IN_DIM];
__device__ float g_qkvb[(size_t)NROWS * NOUT];
__device__ float g_q[(size_t)BSZ*NH*SLEN*DH];
__device__ float g_k[(size_t)BSZ*NH*SLEN*DH];
__device__ float g_v[(size_t)BSZ*NH*SLEN*DH];
__device__ float g_beta[(size_t)BSZ*NH*SLEN];
__device__ __nv_bfloat16 g_o_hi[(size_t)NROWS * IN_DIM];
__device__ __nv_bfloat16 g_o_lo[(size_t)NROWS * IN_DIM];
__device__ __nv_bfloat16 g_ws_t_hi[(size_t)NOUT_PAD * IN_DIM];
__device__ __nv_bfloat16 g_ws_t_lo[(size_t)NOUT_PAD * IN_DIM];
__device__ __nv_bfloat16 g_wo_t_hi[(size_t)IN_DIM * IN_DIM];
__device__ __nv_bfloat16 g_wo_t_lo[(size_t)IN_DIM * IN_DIM];

// ---------------- helpers ----------------
__device__ __forceinline__ void cp_async16(void* smem_dst, const void* gsrc) {
    unsigned s = (unsigned)__cvta_generic_to_shared(smem_dst);
    asm volatile("cp.async.cg.shared.global [%0], [%1], 16;\n" :: "r"(s), "l"(gsrc));
}
__device__ __forceinline__ float elu_p1(float x) {
    return x > 0.f ? x + 1.f : __expf(x);
}
__device__ __forceinline__ void split_bf16(float x, __nv_bfloat16& hi, __nv_bfloat16& lo) {
    hi = __float2bfloat16(x);
    lo = __float2bfloat16(x - __bfloat162float(hi));
}
__device__ __forceinline__ void mma_bf16(float* d, const uint32_t* a, const uint32_t* b) {
    asm volatile("mma.sync.aligned.m16n8k16.row.col.f32.bf16.bf16.f32 "
        "{%0,%1,%2,%3}, {%4,%5,%6,%7}, {%8,%9}, {%0,%1,%2,%3};"
        : "+f"(d[0]), "+f"(d[1]), "+f"(d[2]), "+f"(d[3])
        : "r"(a[0]), "r"(a[1]), "r"(a[2]), "r"(a[3]), "r"(b[0]), "r"(b[1]));
}
__device__ __forceinline__ void ldsm_x4(uint32_t* r, uint32_t saddr) {
    asm volatile("ldmatrix.sync.aligned.m8n8.x4.shared.b16 {%0,%1,%2,%3}, [%4];"
        : "=r"(r[0]), "=r"(r[1]), "=r"(r[2]), "=r"(r[3]) : "r"(saddr));
}
__device__ __forceinline__ void ldsm_x2(uint32_t* r, uint32_t saddr) {
    asm volatile("ldmatrix.sync.aligned.m8n8.x2.shared.b16 {%0,%1}, [%2];"
        : "=r"(r[0]), "=r"(r[1]) : "r"(saddr));
}

// ---------------- split+transpose weights: W[K][N] f32 -> T_hi/T_lo[Npad][K] bf16 ----------------
__global__ __launch_bounds__(256) void split_transpose(
    const float* __restrict__ W, __nv_bfloat16* __restrict__ Th,
    __nv_bfloat16* __restrict__ Tl, int K, int N)
{
    __shared__ float tile[32][33];
    int n0 = blockIdx.x * 32, k0 = blockIdx.y * 32;
    int tx = threadIdx.x, ty = threadIdx.y;   // 32 x 8
    #pragma unroll
    for (int i = 0; i < 32; i += 8) {
        int k = k0 + ty + i, n = n0 + tx;
        tile[ty + i][tx] = (n < N) ? W[(size_t)k * N + n] : 0.f;
    }
    __syncthreads();
    #pragma unroll
    for (int i = 0; i < 32; i += 8) {
        int n = n0 + ty + i, k = k0 + tx;
        float v = tile[tx][ty + i];
        __nv_bfloat16 hi, lo;
        split_bf16(v, hi, lo);
        Th[(size_t)n * K + k] = hi;
        Tl[(size_t)n * K + k] = lo;
    }
}

// ---------------- LayerNorm: one block per row; writes split bf16 ----------------
__global__ __launch_bounds__(256) void ln_kernel(
    const float* __restrict__ x, const float* __restrict__ w,
    const float* __restrict__ b, __nv_bfloat16* __restrict__ hhi,
    __nv_bfloat16* __restrict__ hlo)
{
    int row = blockIdx.x;
    int t = threadIdx.x;
    const float4* xr = (const float4*)(x + (size_t)row * IN_DIM);
    float4 v = xr[t];
    float s  = v.x + v.y + v.z + v.w;
    float ss = v.x*v.x + v.y*v.y + v.z*v.z + v.w*v.w;
    #pragma unroll
    for (int o = 16; o; o >>= 1) {
        s  += __shfl_xor_sync(0xffffffffu, s,  o);
        ss += __shfl_xor_sync(0xffffffffu, ss, o);
    }
    __shared__ float rs[8], rss[8];
    if ((t & 31) == 0) { rs[t >> 5] = s; rss[t >> 5] = ss; }
    __syncthreads();
    float S = 0.f, SS = 0.f;
    #pragma unroll
    for (int i = 0; i < 8; i++) { S += rs[i]; SS += rss[i]; }
    float mu = S * (1.f / IN_DIM);
    float var = SS * (1.f / IN_DIM) - mu * mu;
    float rstd = rsqrtf(var + 1e-5f);
    float4 wv = ((const float4*)w)[t];
    float4 bv = ((const float4*)b)[t];
    float o0 = (v.x - mu) * rstd * wv.x + bv.x;
    float o1 = (v.y - mu) * rstd * wv.y + bv.y;
    float o2 = (v.z - mu) * rstd * wv.z + bv.z;
    float o3 = (v.w - mu) * rstd * wv.w + bv.w;
    __nv_bfloat16 h0,l0,h1,l1,h2,l2,h3,l3;
    split_bf16(o0,h0,l0); split_bf16(o1,h1,l1);
    split_bf16(o2,h2,l2); split_bf16(o3,h3,l3);
    size_t base = (size_t)row * IN_DIM;
    ((__nv_bfloat162*)(hhi + base))[2*t]   = __nv_bfloat162(h0, h1);
    ((__nv_bfloat162*)(hhi + base))[2*t+1] = __nv_bfloat162(h2, h3);
    ((__nv_bfloat162*)(hlo + base))[2*t]   = __nv_bfloat162(l0, l1);
    ((__nv_bfloat162*)(hlo + base))[2*t+1] = __nv_bfloat162(l2, l3);
}

// ---------------- bf16x3 tensor-core GEMM (ldmatrix, XOR-swizzle, 3-stage) ----------------
#define KT  32
#define ARR_U32 (128 * 16)           // 2048 u32 = 8KB per array
#define STAGE_U32 (4 * ARR_U32)      // 32KB per stage
#define GEMM_SMEM_BYTES (3 * STAGE_U32 * 4)   // 98304

__global__ __launch_bounds__(256, 2) void gemm_bf16x3(
    const __nv_bfloat16* __restrict__ Ah, const __nv_bfloat16* __restrict__ Al,
    const __nv_bfloat16* __restrict__ Bh, const __nv_bfloat16* __restrict__ Bl,
    const float* __restrict__ Res, float* __restrict__ C,
    int N, int K)
{
    extern __shared__ __align__(16) uint32_t dsm[];

    const int tid  = threadIdx.x;
    const int warp = tid >> 5;
    const int lane = tid & 31;
    const int gid  = lane >> 2;
    const int tig  = lane & 3;
    const int wm   = warp & 1;
    const int wn   = warp >> 1;
    const int row0 = blockIdx.y * 128;
    const int col0 = blockIdx.x * 128;

    float acc[4][4][4];
    #pragma unroll
    for (int i = 0; i < 4; i++)
        #pragma unroll
        for (int j = 0; j < 4; j++)
            #pragma unroll
            for (int k = 0; k < 4; k++) acc[i][j][k] = 0.f;

    const int nk = K / KT;
    const uint32_t smem0 = (uint32_t)__cvta_generic_to_shared(dsm);

    auto load_stage = [&](int kt) {
        const int k0 = kt * KT;
        uint32_t* sb = dsm + (kt % 3) * STAGE_U32;
        #pragma unroll
        for (int half = 0; half < 2; half++) {
            int c2 = tid + half * 256;
            int r = c2 >> 2, f = c2 & 3;
            int fs = f ^ ((r >> 1) & 3);
            size_t aoff = (size_t)(row0 + r) * K + k0 + f * 8;
            size_t boff = (size_t)(col0 + r) * K + k0 + f * 8;
            uint32_t* dst = sb + r * 16 + fs * 4;
            cp_async16(dst,               Ah + aoff);
            cp_async16(dst + ARR_U32,     Al + aoff);
            cp_async16(dst + 2 * ARR_U32, Bh + boff);
            cp_async16(dst + 3 * ARR_U32, Bl + boff);
        }
        asm volatile("cp.async.commit_group;\n" ::);
    };

    load_stage(0);
    load_stage(1);

    const int a_sub = lane >> 3;
    const int a_rin = lane & 7;
    const int a_row0 = wm * 64 + (a_sub & 1) * 8 + a_rin;
    const int a_ph  = (a_row0 >> 1) & 3;
    const uint32_t a_byte0 = (uint32_t)(a_row0 * 64);
    const uint32_t a_ch[2] = { (uint32_t)((((a_sub >> 1)    ) ^ a_ph) * 16),
                               (uint32_t)(((2 + (a_sub >> 1)) ^ a_ph) * 16) };
    const int b_row0 = wn * 32 + (lane & 7);
    const int b_ph  = (b_row0 >> 1) & 3;
    const uint32_t b_byte0 = (uint32_t)(b_row0 * 64);
    const int b_sub = (lane >> 3) & 1;
    const uint32_t b_ch[2] = { (uint32_t)(((b_sub    ) ^ b_ph) * 16),
                               (uint32_t)(((2 + b_sub) ^ b_ph) * 16) };

    for (int kt = 0; kt < nk; kt++) {
        asm volatile("cp.async.wait_group 1;\n" ::);
        __syncthreads();
        if (kt + 2 < nk) load_stage(kt + 2);
        else asm volatile("cp.async.commit_group;\n" ::);

        const uint32_t sbase = smem0 + (uint32_t)((kt % 3) * STAGE_U32 * 4);
        const uint32_t sAh = sbase;
        const uint32_t sAl = sbase + ARR_U32 * 4;
        const uint32_t sBh = sbase + 2 * ARR_U32 * 4;
        const uint32_t sBl = sbase + 3 * ARR_U32 * 4;

        #pragma unroll
        for (int kb = 0; kb < 2; kb++) {
            uint32_t ah[4][4], al[4][4];
            #pragma unroll
            for (int mt = 0; mt < 4; mt++) {
                uint32_t off = a_byte0 + (uint32_t)(mt * 16 * 64) + a_ch[kb];
                ldsm_x4(ah[mt], sAh + off);
                ldsm_x4(al[mt], sAl + off);
            }
            uint32_t bh[4][2], bl[4][2];
            #pragma unroll
            for (int nt = 0; nt < 4; nt++) {
                uint32_t off = b_byte0 + (uint32_t)(nt * 8 * 64) + b_ch[kb];
                ldsm_x2(bh[nt], sBh + off);
                ldsm_x2(bl[nt], sBl + off);
            }
            #pragma unroll
            for (int nt = 0; nt < 4; nt++)
                #pragma unroll
                for (int mt = 0; mt < 4; mt++) mma_bf16(acc[mt][nt], ah[mt], bh[nt]);
            #pragma unroll
            for (int nt = 0; nt < 4; nt++)
                #pragma unroll
                for (int mt = 0; mt < 4; mt++) mma_bf16(acc[mt][nt], al[mt], bh[nt]);
            #pragma unroll
            for (int nt = 0; nt < 4; nt++)
                #pragma unroll
                for (int mt = 0; mt < 4; mt++) mma_bf16(acc[mt][nt], ah[mt], bl[nt]);
        }
    }

    #pragma unroll
    for (int mt = 0; mt < 4; mt++) {
        #pragma unroll
        for (int nt = 0; nt < 4; nt++) {
            int r = row0 + wm * 64 + mt * 16 + gid;
            int c = col0 + wn * 32 + nt * 8 + 2 * tig;
            if (c < N) {
                size_t o0 = (size_t)r * N + c;
                size_t o1 = (size_t)(r + 8) * N + c;
                float2 v0 = make_float2(acc[mt][nt][0], acc[mt][nt][1]);
                float2 v1 = make_float2(acc[mt][nt][2], acc[mt][nt][3]);
                if (Res) {
                    float2 r0 = *(const float2*)&Res[o0];
                    float2 r1 = *(const float2*)&Res[o1];
                    v0.x += r0.x; v0.y += r0.y;
                    v1.x += r1.x; v1.y += r1.y;
                }
                *(float2*)&C[o0] = v0;
                *(float2*)&C[o1] = v1;
            }
        }
    }
}

// ---------------- transform: elu_p1+sum_norm on q,k; sigmoid beta; relayout ----------------
__global__ __launch_bounds__(256) void transform_kernel(
    const float* __restrict__ qkvb,
    float* __restrict__ Q, float* __restrict__ Kk,
    float* __restrict__ V, float* __restrict__ Beta)
{
    int gw   = blockIdx.x * 8 + (threadIdx.x >> 5);
    int lane = threadIdx.x & 31;
    int h  = gw & 15;
    int tb = gw >> 4;
    int b  = tb & 7;
    int t  = tb >> 3;
    const float* src = qkvb + (size_t)tb * NOUT + h * (3*DH + 1);
    size_t dst = ((size_t)(b * NH + h) * SLEN + t) * DH;

    float q0 = elu_p1(src[lane]);
    float q1 = elu_p1(src[lane + 32]);
    float s = q0 + q1;
    #pragma unroll
    for (int o = 16; o; o >>= 1) s += __shfl_xor_sync(0xffffffffu, s, o);
    float inv = 1.f / s;
    Q[dst + lane]      = q0 * inv;
    Q[dst + lane + 32] = q1 * inv;

    float k0 = elu_p1(src[64 + lane]);
    float k1 = elu_p1(src[96 + lane]);
    s = k0 + k1;
    #pragma unroll
    for (int o = 16; o; o >>= 1) s += __shfl_xor_sync(0xffffffffu, s, o);
    inv = 1.f / s;
    Kk[dst + lane]      = k0 * inv;
    Kk[dst + lane + 32] = k1 * inv;

    V[dst + lane]      = src[128 + lane];
    V[dst + lane + 32] = src[160 + lane];

    if (lane == 0) {
        float x = src[192];
        Beta[(size_t)(b * NH + h) * SLEN + t] = 1.f / (1.f + __expf(-x));
    }
}

// ---------------- delta-rule scan v2: 1024 blocks x 2 warps (8 rows/block) ----------------
// Warp layout: rloc = lane>>3 (4 rows), g = lane&7 (8 cols each) -> W[8] regs.
// Shared k/q ring per block (x8 L2 amplification), double-buffered CH=16 chunks.
#define CH 16
__global__ __launch_bounds__(64) void scan_kernel(
    const float* __restrict__ Q, const float* __restrict__ Kk,
    const float* __restrict__ V, const float* __restrict__ Beta,
    __nv_bfloat16* __restrict__ Ohi, __nv_bfloat16* __restrict__ Olo)
{
    __shared__ __align__(16) float sk[2][CH][64];
    __shared__ __align__(16) float sq[2][CH][64];
    __shared__ __align__(16) float sv[2][CH][8];
    __shared__ __align__(16) float sb[2][CH];

    const int bh = blockIdx.x >> 3;       // 0..127
    const int w8 = (blockIdx.x & 7) * 8;  // row-octet base
    const int b = bh >> 4, h = bh & 15;
    const float* Kp = Kk   + (size_t)bh * SLEN * DH;
    const float* Vp = V    + (size_t)bh * SLEN * DH;
    const float* Qp = Q    + (size_t)bh * SLEN * DH;
    const float* Bp = Beta + (size_t)bh * SLEN;
    const int tid  = threadIdx.x;
    const int wid  = tid >> 5;            // 0..1
    const int lane = tid & 31;
    const int rloc = lane >> 3;           // 0..3
    const int g    = lane & 7;            // 0..7
    const int vrow = wid * 4 + rloc;      // 0..7 within block
    const int i    = w8 + vrow;           // global row 0..63

    float W[8];
    #pragma unroll
    for (int m = 0; m < 8; m++) W[m] = 0.f;

    auto issue = [&](int c) {
        int buf = c & 1;
        int t0 = c * CH;
        // k,q: 256 float4 chunks each, 64 threads -> 4 per thread per array
        #pragma unroll
        for (int j = 0; j < 4; j++) {
            int idx = tid + j * 64;            // 0..255
            int tt = idx >> 4, f = idx & 15;
            cp_async16(&sk[buf][tt][f * 4], Kp + (size_t)(t0 + tt) * DH + f * 4);
            cp_async16(&sq[buf][tt][f * 4], Qp + (size_t)(t0 + tt) * DH + f * 4);
        }
        // v: 8 floats per step (rows w8..w8+7) = 2 chunks x 16 steps = 32 chunks
        if (tid < 32) {
            int tt = tid >> 1, hf = tid & 1;
            cp_async16(&sv[buf][tt][hf * 4], Vp + (size_t)(t0 + tt) * DH + w8 + hf * 4);
        }
        // beta: 16 floats = 4 chunks
        if (tid >= 60) cp_async16(&sb[buf][(tid - 60) * 4], Bp + t0 + (tid - 60) * 4);
        asm volatile("cp.async.commit_group;\n" ::);
    };

    issue(0); issue(1);

    const int NC = SLEN / CH;
    const size_t obase = (size_t)b * IN_DIM + h * DH + i;

    for (int c = 0; c < NC; c++) {
        asm volatile("cp.async.wait_group 1;\n" ::);
        __syncthreads();                        // all warps' chunk-c data visible
        const int buf = c & 1;

        #pragma unroll 4
        for (int tt = 0; tt < CH; tt++) {
            float kv[8], qv[8];
            #pragma unroll
            for (int m = 0; m < 2; m++) {
                float4 k4 = *(const float4*)&sk[buf][tt][g * 8 + m * 4];
                kv[m*4+0] = k4.x; kv[m*4+1] = k4.y; kv[m*4+2] = k4.z; kv[m*4+3] = k4.w;
                float4 q4 = *(const float4*)&sq[buf][tt][g * 8 + m * 4];
                qv[m*4+0] = q4.x; qv[m*4+1] = q4.y; qv[m*4+2] = q4.z; qv[m*4+3] = q4.w;
            }
            float vi   = sv[buf][tt][vrow];
            float beta = sb[buf][tt];

            // v_old[i] = sum_j W[i,j] k[j] : 8 partial FMAs + 3-shfl reduce over g
            float pk0 = 0.f, pk1 = 0.f;
            #pragma unroll
            for (int m = 0; m < 4; m++) {
                pk0 = fmaf(W[m],     kv[m],     pk0);
                pk1 = fmaf(W[m + 4], kv[m + 4], pk1);
            }
            float pk = pk0 + pk1;
            pk += __shfl_xor_sync(0xffffffffu, pk, 1);
            pk += __shfl_xor_sync(0xffffffffu, pk, 2);
            pk += __shfl_xor_sync(0xffffffffu, pk, 4);

            float delta = beta * (vi - pk);

            float po0 = 0.f, po1 = 0.f;
            #pragma unroll
            for (int m = 0; m < 4; m++) {
                W[m]     = fmaf(delta, kv[m],     W[m]);
                po0      = fmaf(W[m],  qv[m],     po0);
                W[m + 4] = fmaf(delta, kv[m + 4], W[m + 4]);
                po1      = fmaf(W[m + 4], qv[m + 4], po1);
            }
            float po = po0 + po1;
            po += __shfl_xor_sync(0xffffffffu, po, 1);
            po += __shfl_xor_sync(0xffffffffu, po, 2);
            po += __shfl_xor_sync(0xffffffffu, po, 4);

            if (g == 0) {
                int t = c * CH + tt;
                size_t off = (size_t)t * (BSZ * IN_DIM) + obase;
                __nv_bfloat16 hi, lo;
                split_bf16(po, hi, lo);
                Ohi[off] = hi;
                Olo[off] = lo;
            }
        }
        __syncthreads();                        // all warps done reading buf c
        if (c + 2 < NC) issue(c + 2);
        else asm volatile("cp.async.commit_group;\n" ::);
    }
}

// ---------------- launcher ----------------
extern "C" void kernel_launch(void* const* d_in, const int* in_sizes, int n_in,
                              void* d_out, int out_size)
{
    const float* x      = (const float*)d_in[0];
    const float* ln_w   = (const float*)d_in[1];
    const float* ln_b   = (const float*)d_in[2];
    const float* w_slow = (const float*)d_in[3];
    const float* w_out  = (const float*)d_in[4];
    float* out = (float*)d_out;

    float *p_qkvb, *p_q, *p_k, *p_v, *p_beta;
    __nv_bfloat16 *p_h_hi, *p_h_lo, *p_o_hi, *p_o_lo;
    __nv_bfloat16 *p_ws_hi, *p_ws_lo, *p_wo_hi, *p_wo_lo;
    cudaGetSymbolAddress((void**)&p_qkvb, g_qkvb);
    cudaGetSymbolAddress((void**)&p_q,    g_q);
    cudaGetSymbolAddress((void**)&p_k,    g_k);
    cudaGetSymbolAddress((void**)&p_v,    g_v);
    cudaGetSymbolAddress((void**)&p_beta, g_beta);
    cudaGetSymbolAddress((void**)&p_h_hi, g_h_hi);
    cudaGetSymbolAddress((void**)&p_h_lo, g_h_lo);
    cudaGetSymbolAddress((void**)&p_o_hi, g_o_hi);
    cudaGetSymbolAddress((void**)&p_o_lo, g_o_lo);
    cudaGetSymbolAddress((void**)&p_ws_hi, g_ws_t_hi);
    cudaGetSymbolAddress((void**)&p_ws_lo, g_ws_t_lo);
    cudaGetSymbolAddress((void**)&p_wo_hi, g_wo_t_hi);
    cudaGetSymbolAddress((void**)&p_wo_lo, g_wo_t_lo);

    cudaFuncSetAttribute(gemm_bf16x3, cudaFuncAttributeMaxDynamicSharedMemorySize,
                         GEMM_SMEM_BYTES);

    // 0. split+transpose weights
    {
        dim3 blk(32, 8);
        dim3 g1(NOUT_PAD / 32, IN_DIM / 32);
        split_transpose<<<g1, blk>>>(w_slow, p_ws_hi, p_ws_lo, IN_DIM, NOUT);
        dim3 g2(IN_DIM / 32, IN_DIM / 32);
        split_transpose<<<g2, blk>>>(w_out, p_wo_hi, p_wo_lo, IN_DIM, IN_DIM);
    }

    // 1. LayerNorm -> split bf16
    ln_kernel<<<NROWS, 256>>>(x, ln_w, ln_b, p_h_hi, p_h_lo);

    // 2. qkvb = h @ w_slow
    {
        dim3 grid(NOUT_PAD / 128, NROWS / 128);
        gemm_bf16x3<<<grid, 256, GEMM_SMEM_BYTES>>>(p_h_hi, p_h_lo, p_ws_hi, p_ws_lo,
                                                    nullptr, p_qkvb, NOUT, IN_DIM);
    }

    // 3. transform
    transform_kernel<<<(NROWS * NH) / 8, 256>>>(p_qkvb, p_q, p_k, p_v, p_beta);

    // 4. delta-rule scan (1024 blocks x 2 warps, 8 rows/block)
    scan_kernel<<<BSZ * NH * 8, 64>>>(p_q, p_k, p_v, p_beta, p_o_hi, p_o_lo);

    // 5. out = x + scan_out @ w_out
    {
        dim3 grid(IN_DIM / 128, NROWS / 128);
        gemm_bf16x3<<<grid, 256, GEMM_SMEM_BYTES>>>(p_o_hi, p_o_lo, p_wo_hi, p_wo_lo,
                                                    x, out, IN_DIM, IN_DIM);
    }
}

// round 10
// speedup vs baseline: 1.0346x; 1.0346x over previous
#include <cuda_runtime.h>
#include <cuda_bf16.h>
#include <cstdint>

// Problem constants
#define SLEN   2048
#define BSZ    8
#define IN_DIM 1024
#define NH     16
#define DH     64
#define NROWS  (SLEN*BSZ)              // 16384
#define NOUT   (NH*(3*DH+1))           // 3088
#define NOUT_PAD 3200

// ---------------- device scratch ----------------
__device__ __nv_bfloat16 g_h_hi[(size_t)NROWS * IN_DIM];
__device__ __nv_bfloat16 g_h_lo[(size_t)NROWS * IN_DIM];
__device__ float g_qkvb[(size_t)NROWS * NOUT];
__device__ float g_q[(size_t)BSZ*NH*SLEN*DH];
__device__ float g_k[(size_t)BSZ*NH*SLEN*DH];
__device__ float g_v[(size_t)BSZ*NH*SLEN*DH];
__device__ float g_beta[(size_t)BSZ*NH*SLEN];
__device__ __nv_bfloat16 g_o_hi[(size_t)NROWS * IN_DIM];
__device__ __nv_bfloat16 g_o_lo[(size_t)NROWS * IN_DIM];
__device__ __nv_bfloat16 g_ws_t_hi[(size_t)NOUT_PAD * IN_DIM];
__device__ __nv_bfloat16 g_ws_t_lo[(size_t)NOUT_PAD * IN_DIM];
__device__ __nv_bfloat16 g_wo_t_hi[(size_t)IN_DIM * IN_DIM];
__device__ __nv_bfloat16 g_wo_t_lo[(size_t)IN_DIM * IN_DIM];

// ---------------- helpers ----------------
__device__ __forceinline__ void cp_async16(void* smem_dst, const void* gsrc) {
    unsigned s = (unsigned)__cvta_generic_to_shared(smem_dst);
    asm volatile("cp.async.cg.shared.global [%0], [%1], 16;\n" :: "r"(s), "l"(gsrc));
}
__device__ __forceinline__ float elu_p1(float x) {
    return x > 0.f ? x + 1.f : __expf(x);
}
__device__ __forceinline__ void split_bf16(float x, __nv_bfloat16& hi, __nv_bfloat16& lo) {
    hi = __float2bfloat16(x);
    lo = __float2bfloat16(x - __bfloat162float(hi));
}
__device__ __forceinline__ void mma_bf16(float* d, const uint32_t* a, const uint32_t* b) {
    asm volatile("mma.sync.aligned.m16n8k16.row.col.f32.bf16.bf16.f32 "
        "{%0,%1,%2,%3}, {%4,%5,%6,%7}, {%8,%9}, {%0,%1,%2,%3};"
        : "+f"(d[0]), "+f"(d[1]), "+f"(d[2]), "+f"(d[3])
        : "r"(a[0]), "r"(a[1]), "r"(a[2]), "r"(a[3]), "r"(b[0]), "r"(b[1]));
}
__device__ __forceinline__ void ldsm_x4(uint32_t* r, uint32_t saddr) {
    asm volatile("ldmatrix.sync.aligned.m8n8.x4.shared.b16 {%0,%1,%2,%3}, [%4];"
        : "=r"(r[0]), "=r"(r[1]), "=r"(r[2]), "=r"(r[3]) : "r"(saddr));
}
__device__ __forceinline__ void ldsm_x2(uint32_t* r, uint32_t saddr) {
    asm volatile("ldmatrix.sync.aligned.m8n8.x2.shared.b16 {%0,%1}, [%2];"
        : "=r"(r[0]), "=r"(r[1]) : "r"(saddr));
}

// ---------------- split+transpose weights: W[K][N] f32 -> T_hi/T_lo[Npad][K] bf16 ----------------
__global__ __launch_bounds__(256) void split_transpose(
    const float* __restrict__ W, __nv_bfloat16* __restrict__ Th,
    __nv_bfloat16* __restrict__ Tl, int K, int N)
{
    __shared__ float tile[32][33];
    int n0 = blockIdx.x * 32, k0 = blockIdx.y * 32;
    int tx = threadIdx.x, ty = threadIdx.y;   // 32 x 8
    #pragma unroll
    for (int i = 0; i < 32; i += 8) {
        int k = k0 + ty + i, n = n0 + tx;
        tile[ty + i][tx] = (n < N) ? W[(size_t)k * N + n] : 0.f;
    }
    __syncthreads();
    #pragma unroll
    for (int i = 0; i < 32; i += 8) {
        int n = n0 + ty + i, k = k0 + tx;
        float v = tile[tx][ty + i];
        __nv_bfloat16 hi, lo;
        split_bf16(v, hi, lo);
        Th[(size_t)n * K + k] = hi;
        Tl[(size_t)n * K + k] = lo;
    }
}

// ---------------- LayerNorm: one block per row; writes split bf16 ----------------
__global__ __launch_bounds__(256) void ln_kernel(
    const float* __restrict__ x, const float* __restrict__ w,
    const float* __restrict__ b, __nv_bfloat16* __restrict__ hhi,
    __nv_bfloat16* __restrict__ hlo)
{
    int row = blockIdx.x;
    int t = threadIdx.x;
    const float4* xr = (const float4*)(x + (size_t)row * IN_DIM);
    float4 v = xr[t];
    float s  = v.x + v.y + v.z + v.w;
    float ss = v.x*v.x + v.y*v.y + v.z*v.z + v.w*v.w;
    #pragma unroll
    for (int o = 16; o; o >>= 1) {
        s  += __shfl_xor_sync(0xffffffffu, s,  o);
        ss += __shfl_xor_sync(0xffffffffu, ss, o);
    }
    __shared__ float rs[8], rss[8];
    if ((t & 31) == 0) { rs[t >> 5] = s; rss[t >> 5] = ss; }
    __syncthreads();
    float S = 0.f, SS = 0.f;
    #pragma unroll
    for (int i = 0; i < 8; i++) { S += rs[i]; SS += rss[i]; }
    float mu = S * (1.f / IN_DIM);
    float var = SS * (1.f / IN_DIM) - mu * mu;
    float rstd = rsqrtf(var + 1e-5f);
    float4 wv = ((const float4*)w)[t];
    float4 bv = ((const float4*)b)[t];
    float o0 = (v.x - mu) * rstd * wv.x + bv.x;
    float o1 = (v.y - mu) * rstd * wv.y + bv.y;
    float o2 = (v.z - mu) * rstd * wv.z + bv.z;
    float o3 = (v.w - mu) * rstd * wv.w + bv.w;
    __nv_bfloat16 h0,l0,h1,l1,h2,l2,h3,l3;
    split_bf16(o0,h0,l0); split_bf16(o1,h1,l1);
    split_bf16(o2,h2,l2); split_bf16(o3,h3,l3);
    size_t base = (size_t)row * IN_DIM;
    ((__nv_bfloat162*)(hhi + base))[2*t]   = __nv_bfloat162(h0, h1);
    ((__nv_bfloat162*)(hhi + base))[2*t+1] = __nv_bfloat162(h2, h3);
    ((__nv_bfloat162*)(hlo + base))[2*t]   = __nv_bfloat162(l0, l1);
    ((__nv_bfloat162*)(hlo + base))[2*t+1] = __nv_bfloat162(l2, l3);
}

// ---------------- bf16x3 tensor-core GEMM (ldmatrix, XOR-swizzle, 3-stage) ----------------
#define KT  32
#define ARR_U32 (128 * 16)           // 2048 u32 = 8KB per array
#define STAGE_U32 (4 * ARR_U32)      // 32KB per stage
#define GEMM_SMEM_BYTES (3 * STAGE_U32 * 4)   // 98304

__global__ __launch_bounds__(256, 2) void gemm_bf16x3(
    const __nv_bfloat16* __restrict__ Ah, const __nv_bfloat16* __restrict__ Al,
    const __nv_bfloat16* __restrict__ Bh, const __nv_bfloat16* __restrict__ Bl,
    const float* __restrict__ Res, float* __restrict__ C,
    int N, int K)
{
    extern __shared__ __align__(16) uint32_t dsm[];

    const int tid  = threadIdx.x;
    const int warp = tid >> 5;
    const int lane = tid & 31;
    const int gid  = lane >> 2;
    const int tig  = lane & 3;
    const int wm   = warp & 1;
    const int wn   = warp >> 1;
    const int row0 = blockIdx.y * 128;
    const int col0 = blockIdx.x * 128;

    float acc[4][4][4];
    #pragma unroll
    for (int i = 0; i < 4; i++)
        #pragma unroll
        for (int j = 0; j < 4; j++)
            #pragma unroll
            for (int k = 0; k < 4; k++) acc[i][j][k] = 0.f;

    const int nk = K / KT;
    const uint32_t smem0 = (uint32_t)__cvta_generic_to_shared(dsm);

    auto load_stage = [&](int kt) {
        const int k0 = kt * KT;
        uint32_t* sb = dsm + (kt % 3) * STAGE_U32;
        #pragma unroll
        for (int half = 0; half < 2; half++) {
            int c2 = tid + half * 256;
            int r = c2 >> 2, f = c2 & 3;
            int fs = f ^ ((r >> 1) & 3);
            size_t aoff = (size_t)(row0 + r) * K + k0 + f * 8;
            size_t boff = (size_t)(col0 + r) * K + k0 + f * 8;
            uint32_t* dst = sb + r * 16 + fs * 4;
            cp_async16(dst,               Ah + aoff);
            cp_async16(dst + ARR_U32,     Al + aoff);
            cp_async16(dst + 2 * ARR_U32, Bh + boff);
            cp_async16(dst + 3 * ARR_U32, Bl + boff);
        }
        asm volatile("cp.async.commit_group;\n" ::);
    };

    load_stage(0);
    load_stage(1);

    const int a_sub = lane >> 3;
    const int a_rin = lane & 7;
    const int a_row0 = wm * 64 + (a_sub & 1) * 8 + a_rin;
    const int a_ph  = (a_row0 >> 1) & 3;
    const uint32_t a_byte0 = (uint32_t)(a_row0 * 64);
    const uint32_t a_ch[2] = { (uint32_t)((((a_sub >> 1)    ) ^ a_ph) * 16),
                               (uint32_t)(((2 + (a_sub >> 1)) ^ a_ph) * 16) };
    const int b_row0 = wn * 32 + (lane & 7);
    const int b_ph  = (b_row0 >> 1) & 3;
    const uint32_t b_byte0 = (uint32_t)(b_row0 * 64);
    const int b_sub = (lane >> 3) & 1;
    const uint32_t b_ch[2] = { (uint32_t)(((b_sub    ) ^ b_ph) * 16),
                               (uint32_t)(((2 + b_sub) ^ b_ph) * 16) };

    for (int kt = 0; kt < nk; kt++) {
        asm volatile("cp.async.wait_group 1;\n" ::);
        __syncthreads();
        if (kt + 2 < nk) load_stage(kt + 2);
        else asm volatile("cp.async.commit_group;\n" ::);

        const uint32_t sbase = smem0 + (uint32_t)((kt % 3) * STAGE_U32 * 4);
        const uint32_t sAh = sbase;
        const uint32_t sAl = sbase + ARR_U32 * 4;
        const uint32_t sBh = sbase + 2 * ARR_U32 * 4;
        const uint32_t sBl = sbase + 3 * ARR_U32 * 4;

        #pragma unroll
        for (int kb = 0; kb < 2; kb++) {
            uint32_t ah[4][4], al[4][4];
            #pragma unroll
            for (int mt = 0; mt < 4; mt++) {
                uint32_t off = a_byte0 + (uint32_t)(mt * 16 * 64) + a_ch[kb];
                ldsm_x4(ah[mt], sAh + off);
                ldsm_x4(al[mt], sAl + off);
            }
            uint32_t bh[4][2], bl[4][2];
            #pragma unroll
            for (int nt = 0; nt < 4; nt++) {
                uint32_t off = b_byte0 + (uint32_t)(nt * 8 * 64) + b_ch[kb];
                ldsm_x2(bh[nt], sBh + off);
                ldsm_x2(bl[nt], sBl + off);
            }
            #pragma unroll
            for (int nt = 0; nt < 4; nt++)
                #pragma unroll
                for (int mt = 0; mt < 4; mt++) mma_bf16(acc[mt][nt], ah[mt], bh[nt]);
            #pragma unroll
            for (int nt = 0; nt < 4; nt++)
                #pragma unroll
                for (int mt = 0; mt < 4; mt++) mma_bf16(acc[mt][nt], al[mt], bh[nt]);
            #pragma unroll
            for (int nt = 0; nt < 4; nt++)
                #pragma unroll
                for (int mt = 0; mt < 4; mt++) mma_bf16(acc[mt][nt], ah[mt], bl[nt]);
        }
    }

    #pragma unroll
    for (int mt = 0; mt < 4; mt++) {
        #pragma unroll
        for (int nt = 0; nt < 4; nt++) {
            int r = row0 + wm * 64 + mt * 16 + gid;
            int c = col0 + wn * 32 + nt * 8 + 2 * tig;
            if (c < N) {
                size_t o0 = (size_t)r * N + c;
                size_t o1 = (size_t)(r + 8) * N + c;
                float2 v0 = make_float2(acc[mt][nt][0], acc[mt][nt][1]);
                float2 v1 = make_float2(acc[mt][nt][2], acc[mt][nt][3]);
                if (Res) {
                    float2 r0 = *(const float2*)&Res[o0];
                    float2 r1 = *(const float2*)&Res[o1];
                    v0.x += r0.x; v0.y += r0.y;
                    v1.x += r1.x; v1.y += r1.y;
                }
                *(float2*)&C[o0] = v0;
                *(float2*)&C[o1] = v1;
            }
        }
    }
}

// ---------------- transform: elu_p1+sum_norm on q,k; sigmoid beta; relayout ----------------
__global__ __launch_bounds__(256) void transform_kernel(
    const float* __restrict__ qkvb,
    float* __restrict__ Q, float* __restrict__ Kk,
    float* __restrict__ V, float* __restrict__ Beta)
{
    int gw   = blockIdx.x * 8 + (threadIdx.x >> 5);
    int lane = threadIdx.x & 31;
    int h  = gw & 15;
    int tb = gw >> 4;
    int b  = tb & 7;
    int t  = tb >> 3;
    const float* src = qkvb + (size_t)tb * NOUT + h * (3*DH + 1);
    size_t dst = ((size_t)(b * NH + h) * SLEN + t) * DH;

    float q0 = elu_p1(src[lane]);
    float q1 = elu_p1(src[lane + 32]);
    float s = q0 + q1;
    #pragma unroll
    for (int o = 16; o; o >>= 1) s += __shfl_xor_sync(0xffffffffu, s, o);
    float inv = 1.f / s;
    Q[dst + lane]      = q0 * inv;
    Q[dst + lane + 32] = q1 * inv;

    float k0 = elu_p1(src[64 + lane]);
    float k1 = elu_p1(src[96 + lane]);
    s = k0 + k1;
    #pragma unroll
    for (int o = 16; o; o >>= 1) s += __shfl_xor_sync(0xffffffffu, s, o);
    inv = 1.f / s;
    Kk[dst + lane]      = k0 * inv;
    Kk[dst + lane + 32] = k1 * inv;

    V[dst + lane]      = src[128 + lane];
    V[dst + lane + 32] = src[160 + lane];

    if (lane == 0) {
        float x = src[192];
        Beta[(size_t)(b * NH + h) * SLEN + t] = 1.f / (1.f + __expf(-x));
    }
}

// ---------------- delta-rule scan v3: 2-step blocked, one WARP per (head, octet) ----------------
// lane: row rloc = lane>>2 (8 rows), col group g = lane&3 (16 cols). W[16] regs.
// Per 2 steps: pk1=W·k1, pk2=W·k2, kk=k1·k2 (one reduce phase), then
// d1 = b1(v1-pk1); d2 = b2(v2-pk2-d1*kk); W+=d1k1; po1=W·q1; W+=d2k2; po2=W·q2.
#define CH 16
__global__ __launch_bounds__(32) void scan_kernel(
    const float* __restrict__ Q, const float* __restrict__ Kk,
    const float* __restrict__ V, const float* __restrict__ Beta,
    __nv_bfloat16* __restrict__ Ohi, __nv_bfloat16* __restrict__ Olo)
{
    __shared__ __align__(16) float sk[2][CH][64];
    __shared__ __align__(16) float sq[2][CH][64];
    __shared__ __align__(16) float sv[2][CH][8];
    __shared__ __align__(16) float sb[2][CH];

    const int bh = blockIdx.x >> 3;
    const int w  = blockIdx.x & 7;
    const int b = bh >> 4, h = bh & 15;
    const float* Kp = Kk   + (size_t)bh * SLEN * DH;
    const float* Vp = V    + (size_t)bh * SLEN * DH;
    const float* Qp = Q    + (size_t)bh * SLEN * DH;
    const float* Bp = Beta + (size_t)bh * SLEN;
    const int lane = threadIdx.x;
    const int rloc = lane >> 2;
    const int g = lane & 3;

    float W[16];
    #pragma unroll
    for (int m = 0; m < 16; m++) W[m] = 0.f;

    auto issue = [&](int c) {
        int buf = c & 1;
        int t0 = c * CH;
        #pragma unroll
        for (int j = 0; j < 8; j++) {
            int idx = lane + j * 32;
            int tt = idx >> 4, f = idx & 15;
            cp_async16(&sk[buf][tt][f * 4], Kp + (size_t)(t0 + tt) * DH + f * 4);
        }
        #pragma unroll
        for (int j = 0; j < 8; j++) {
            int idx = lane + j * 32;
            int tt = idx >> 4, f = idx & 15;
            cp_async16(&sq[buf][tt][f * 4], Qp + (size_t)(t0 + tt) * DH + f * 4);
        }
        {
            int tt = lane >> 1, hf = lane & 1;
            cp_async16(&sv[buf][tt][hf * 4], Vp + (size_t)(t0 + tt) * DH + w * 8 + hf * 4);
        }
        if (lane < 4) cp_async16(&sb[buf][lane * 4], Bp + t0 + lane * 4);
        asm volatile("cp.async.commit_group;\n" ::);
    };

    issue(0); issue(1);

    const int NC = SLEN / CH;
    const size_t obase = (size_t)b * IN_DIM + h * DH + w * 8 + rloc;

    for (int c = 0; c < NC; c++) {
        asm volatile("cp.async.wait_group 1;\n" ::);
        __syncwarp();
        const int buf = c & 1;

        #pragma unroll 2
        for (int p = 0; p < CH / 2; p++) {
            const int t1 = 2 * p, t2 = 2 * p + 1;
            float k1[16], k2[16];
            #pragma unroll
            for (int m = 0; m < 4; m++) {
                float4 a4 = *(const float4*)&sk[buf][t1][g * 16 + m * 4];
                k1[m*4+0] = a4.x; k1[m*4+1] = a4.y; k1[m*4+2] = a4.z; k1[m*4+3] = a4.w;
                float4 b4 = *(const float4*)&sk[buf][t2][g * 16 + m * 4];
                k2[m*4+0] = b4.x; k2[m*4+1] = b4.y; k2[m*4+2] = b4.z; k2[m*4+3] = b4.w;
            }

            // three dots off the same W (+ scalar kk), 2-way acc each
            float pk1a = 0.f, pk1b = 0.f, pk2a = 0.f, pk2b = 0.f, kka = 0.f, kkb = 0.f;
            #pragma unroll
            for (int m = 0; m < 8; m++) {
                pk1a = fmaf(W[m],     k1[m],     pk1a);
                pk1b = fmaf(W[m + 8], k1[m + 8], pk1b);
                pk2a = fmaf(W[m],     k2[m],     pk2a);
                pk2b = fmaf(W[m + 8], k2[m + 8], pk2b);
                kka  = fmaf(k1[m],     k2[m],     kka);
                kkb  = fmaf(k1[m + 8], k2[m + 8], kkb);
            }
            float pk1 = pk1a + pk1b;
            float pk2 = pk2a + pk2b;
            float kk  = kka + kkb;
            pk1 += __shfl_xor_sync(0xffffffffu, pk1, 1);
            pk2 += __shfl_xor_sync(0xffffffffu, pk2, 1);
            kk  += __shfl_xor_sync(0xffffffffu, kk,  1);
            pk1 += __shfl_xor_sync(0xffffffffu, pk1, 2);
            pk2 += __shfl_xor_sync(0xffffffffu, pk2, 2);
            kk  += __shfl_xor_sync(0xffffffffu, kk,  2);

            float v1 = sv[buf][t1][rloc];
            float v2 = sv[buf][t2][rloc];
            float b1 = sb[buf][t1];
            float b2 = sb[buf][t2];

            float d1 = b1 * (v1 - pk1);
            float d2 = b2 * (v2 - pk2 - d1 * kk);

            // W1 = W + d1 k1; po1 = W1 . q1
            float q1v[16];
            #pragma unroll
            for (int m = 0; m < 4; m++) {
                float4 a4 = *(const float4*)&sq[buf][t1][g * 16 + m * 4];
                q1v[m*4+0] = a4.x; q1v[m*4+1] = a4.y; q1v[m*4+2] = a4.z; q1v[m*4+3] = a4.w;
            }
            float po1a = 0.f, po1b = 0.f;
            #pragma unroll
            for (int m = 0; m < 8; m++) {
                W[m]     = fmaf(d1, k1[m],     W[m]);
                po1a     = fmaf(W[m],  q1v[m], po1a);
                W[m + 8] = fmaf(d1, k1[m + 8], W[m + 8]);
                po1b     = fmaf(W[m + 8], q1v[m + 8], po1b);
            }

            // W2 = W1 + d2 k2; po2 = W2 . q2
            float q2v[16];
            #pragma unroll
            for (int m = 0; m < 4; m++) {
                float4 a4 = *(const float4*)&sq[buf][t2][g * 16 + m * 4];
                q2v[m*4+0] = a4.x; q2v[m*4+1] = a4.y; q2v[m*4+2] = a4.z; q2v[m*4+3] = a4.w;
            }
            float po2a = 0.f, po2b = 0.f;
            #pragma unroll
            for (int m = 0; m < 8; m++) {
                W[m]     = fmaf(d2, k2[m],     W[m]);
                po2a     = fmaf(W[m],  q2v[m], po2a);
                W[m + 8] = fmaf(d2, k2[m + 8], W[m + 8]);
                po2b     = fmaf(W[m + 8], q2v[m + 8], po2b);
            }

            // output reduces (off the next-iteration chain)
            float po1 = po1a + po1b;
            float po2 = po2a + po2b;
            po1 += __shfl_xor_sync(0xffffffffu, po1, 1);
            po2 += __shfl_xor_sync(0xffffffffu, po2, 1);
            po1 += __shfl_xor_sync(0xffffffffu, po1, 2);
            po2 += __shfl_xor_sync(0xffffffffu, po2, 2);

            if (g == 0) {
                int tg1 = c * CH + t1;
                size_t off1 = (size_t)tg1 * (BSZ * IN_DIM) + obase;
                size_t off2 = off1 + (BSZ * IN_DIM);
                __nv_bfloat16 hi, lo;
                split_bf16(po1, hi, lo);
                Ohi[off1] = hi; Olo[off1] = lo;
                split_bf16(po2, hi, lo);
                Ohi[off2] = hi; Olo[off2] = lo;
            }
        }
        __syncwarp();
        if (c + 2 < NC) issue(c + 2);
        else asm volatile("cp.async.commit_group;\n" ::);
    }
}

// ---------------- launcher ----------------
extern "C" void kernel_launch(void* const* d_in, const int* in_sizes, int n_in,
                              void* d_out, int out_size)
{
    const float* x      = (const float*)d_in[0];
    const float* ln_w   = (const float*)d_in[1];
    const float* ln_b   = (const float*)d_in[2];
    const float* w_slow = (const float*)d_in[3];
    const float* w_out  = (const float*)d_in[4];
    float* out = (float*)d_out;

    float *p_qkvb, *p_q, *p_k, *p_v, *p_beta;
    __nv_bfloat16 *p_h_hi, *p_h_lo, *p_o_hi, *p_o_lo;
    __nv_bfloat16 *p_ws_hi, *p_ws_lo, *p_wo_hi, *p_wo_lo;
    cudaGetSymbolAddress((void**)&p_qkvb, g_qkvb);
    cudaGetSymbolAddress((void**)&p_q,    g_q);
    cudaGetSymbolAddress((void**)&p_k,    g_k);
    cudaGetSymbolAddress((void**)&p_v,    g_v);
    cudaGetSymbolAddress((void**)&p_beta, g_beta);
    cudaGetSymbolAddress((void**)&p_h_hi, g_h_hi);
    cudaGetSymbolAddress((void**)&p_h_lo, g_h_lo);
    cudaGetSymbolAddress((void**)&p_o_hi, g_o_hi);
    cudaGetSymbolAddress((void**)&p_o_lo, g_o_lo);
    cudaGetSymbolAddress((void**)&p_ws_hi, g_ws_t_hi);
    cudaGetSymbolAddress((void**)&p_ws_lo, g_ws_t_lo);
    cudaGetSymbolAddress((void**)&p_wo_hi, g_wo_t_hi);
    cudaGetSymbolAddress((void**)&p_wo_lo, g_wo_t_lo);

    cudaFuncSetAttribute(gemm_bf16x3, cudaFuncAttributeMaxDynamicSharedMemorySize,
                         GEMM_SMEM_BYTES);

    // 0. split+transpose weights
    {
        dim3 blk(32, 8);
        dim3 g1(NOUT_PAD / 32, IN_DIM / 32);
        split_transpose<<<g1, blk>>>(w_slow, p_ws_hi, p_ws_lo, IN_DIM, NOUT);
        dim3 g2(IN_DIM / 32, IN_DIM / 32);
        split_transpose<<<g2, blk>>>(w_out, p_wo_hi, p_wo_lo, IN_DIM, IN_DIM);
    }

    // 1. LayerNorm -> split bf16
    ln_kernel<<<NROWS, 256>>>(x, ln_w, ln_b, p_h_hi, p_h_lo);

    // 2. qkvb = h @ w_slow
    {
        dim3 grid(NOUT_PAD / 128, NROWS / 128);
        gemm_bf16x3<<<grid, 256, GEMM_SMEM_BYTES>>>(p_h_hi, p_h_lo, p_ws_hi, p_ws_lo,
                                                    nullptr, p_qkvb, NOUT, IN_DIM);
    }

    // 3. transform
    transform_kernel<<<(NROWS * NH) / 8, 256>>>(p_qkvb, p_q, p_k, p_v, p_beta);

    // 4. delta-rule scan (2-step blocked, 1024 blocks x 1 warp)
    scan_kernel<<<BSZ * NH * 8, 32>>>(p_q, p_k, p_v, p_beta, p_o_hi, p_o_lo);

    // 5. out = x + scan_out @ w_out
    {
        dim3 grid(IN_DIM / 128, NROWS / 128);
        gemm_bf16x3<<<grid, 256, GEMM_SMEM_BYTES>>>(p_o_hi, p_o_lo, p_wo_hi, p_wo_lo,
                                                    x, out, IN_DIM, IN_DIM);
    }
}

// round 11
// speedup vs baseline: 1.0794x; 1.0434x over previous
#include <cuda_runtime.h>
#include <cuda_bf16.h>
#include <cuda_fp16.h>
#include <cstdint>

// Problem constants
#define SLEN   2048
#define BSZ    8
#define IN_DIM 1024
#define NH     16
#define DH     64
#define NROWS  (SLEN*BSZ)              // 16384
#define NOUT   (NH*(3*DH+1))           // 3088
#define NOUT_PAD 3200

// ---------------- device scratch ----------------
__device__ __nv_bfloat16 g_h_hi[(size_t)NROWS * IN_DIM];
__device__ __nv_bfloat16 g_h_lo[(size_t)NROWS * IN_DIM];
__device__ float g_qkvb[(size_t)NROWS * NOUT];
__device__ float g_q[(size_t)BSZ*NH*SLEN*DH];
__device__ float g_k[(size_t)BSZ*NH*SLEN*DH];
__device__ float g_v[(size_t)BSZ*NH*SLEN*DH];
__device__ float g_beta[(size_t)BSZ*NH*SLEN];
__device__ __half g_o_hi[(size_t)NROWS * IN_DIM];     // f16 for GEMM2
__device__ __half g_o_lo[(size_t)NROWS * IN_DIM];
__device__ __nv_bfloat16 g_ws_t_hi[(size_t)NOUT_PAD * IN_DIM];
__device__ __nv_bfloat16 g_ws_t_lo[(size_t)NOUT_PAD * IN_DIM];
__device__ __half g_wo_t_hi[(size_t)IN_DIM * IN_DIM]; // f16 for GEMM2
__device__ __half g_wo_t_lo[(size_t)IN_DIM * IN_DIM];

// ---------------- helpers ----------------
__device__ __forceinline__ void cp_async16(void* smem_dst, const void* gsrc) {
    unsigned s = (unsigned)__cvta_generic_to_shared(smem_dst);
    asm volatile("cp.async.cg.shared.global [%0], [%1], 16;\n" :: "r"(s), "l"(gsrc));
}
__device__ __forceinline__ float elu_p1(float x) {
    return x > 0.f ? x + 1.f : __expf(x);
}
__device__ __forceinline__ void split_bf16(float x, __nv_bfloat16& hi, __nv_bfloat16& lo) {
    hi = __float2bfloat16(x);
    lo = __float2bfloat16(x - __bfloat162float(hi));
}
__device__ __forceinline__ void split_f16(float x, __half& hi, __half& lo) {
    hi = __float2half(x);
    lo = __float2half(x - __half2float(hi));
}
__device__ __forceinline__ void mma_bf16(float* d, const uint32_t* a, const uint32_t* b) {
    asm volatile("mma.sync.aligned.m16n8k16.row.col.f32.bf16.bf16.f32 "
        "{%0,%1,%2,%3}, {%4,%5,%6,%7}, {%8,%9}, {%0,%1,%2,%3};"
        : "+f"(d[0]), "+f"(d[1]), "+f"(d[2]), "+f"(d[3])
        : "r"(a[0]), "r"(a[1]), "r"(a[2]), "r"(a[3]), "r"(b[0]), "r"(b[1]));
}
__device__ __forceinline__ void mma_f16(float* d, const uint32_t* a, const uint32_t* b) {
    asm volatile("mma.sync.aligned.m16n8k16.row.col.f32.f16.f16.f32 "
        "{%0,%1,%2,%3}, {%4,%5,%6,%7}, {%8,%9}, {%0,%1,%2,%3};"
        : "+f"(d[0]), "+f"(d[1]), "+f"(d[2]), "+f"(d[3])
        : "r"(a[0]), "r"(a[1]), "r"(a[2]), "r"(a[3]), "r"(b[0]), "r"(b[1]));
}
__device__ __forceinline__ void ldsm_x4(uint32_t* r, uint32_t saddr) {
    asm volatile("ldmatrix.sync.aligned.m8n8.x4.shared.b16 {%0,%1,%2,%3}, [%4];"
        : "=r"(r[0]), "=r"(r[1]), "=r"(r[2]), "=r"(r[3]) : "r"(saddr));
}
__device__ __forceinline__ void ldsm_x2(uint32_t* r, uint32_t saddr) {
    asm volatile("ldmatrix.sync.aligned.m8n8.x2.shared.b16 {%0,%1}, [%2];"
        : "=r"(r[0]), "=r"(r[1]) : "r"(saddr));
}

// ---------------- split+transpose weights (bf16 out): W[K][N] -> T[Npad][K] ----------------
__global__ __launch_bounds__(256) void split_transpose(
    const float* __restrict__ W, __nv_bfloat16* __restrict__ Th,
    __nv_bfloat16* __restrict__ Tl, int K, int N)
{
    __shared__ float tile[32][33];
    int n0 = blockIdx.x * 32, k0 = blockIdx.y * 32;
    int tx = threadIdx.x, ty = threadIdx.y;
    #pragma unroll
    for (int i = 0; i < 32; i += 8) {
        int k = k0 + ty + i, n = n0 + tx;
        tile[ty + i][tx] = (n < N) ? W[(size_t)k * N + n] : 0.f;
    }
    __syncthreads();
    #pragma unroll
    for (int i = 0; i < 32; i += 8) {
        int n = n0 + ty + i, k = k0 + tx;
        float v = tile[tx][ty + i];
        __nv_bfloat16 hi, lo;
        split_bf16(v, hi, lo);
        Th[(size_t)n * K + k] = hi;
        Tl[(size_t)n * K + k] = lo;
    }
}

// ---------------- split+transpose weights (f16 out, for GEMM2's B) ----------------
__global__ __launch_bounds__(256) void split_transpose_f16(
    const float* __restrict__ W, __half* __restrict__ Th,
    __half* __restrict__ Tl, int K, int N)
{
    __shared__ float tile[32][33];
    int n0 = blockIdx.x * 32, k0 = blockIdx.y * 32;
    int tx = threadIdx.x, ty = threadIdx.y;
    #pragma unroll
    for (int i = 0; i < 32; i += 8) {
        int k = k0 + ty + i, n = n0 + tx;
        tile[ty + i][tx] = (n < N) ? W[(size_t)k * N + n] : 0.f;
    }
    __syncthreads();
    #pragma unroll
    for (int i = 0; i < 32; i += 8) {
        int n = n0 + ty + i, k = k0 + tx;
        float v = tile[tx][ty + i];
        __half hi, lo;
        split_f16(v, hi, lo);
        Th[(size_t)n * K + k] = hi;
        Tl[(size_t)n * K + k] = lo;
    }
}

// ---------------- LayerNorm: one block per row; writes split bf16 ----------------
__global__ __launch_bounds__(256) void ln_kernel(
    const float* __restrict__ x, const float* __restrict__ w,
    const float* __restrict__ b, __nv_bfloat16* __restrict__ hhi,
    __nv_bfloat16* __restrict__ hlo)
{
    int row = blockIdx.x;
    int t = threadIdx.x;
    const float4* xr = (const float4*)(x + (size_t)row * IN_DIM);
    float4 v = xr[t];
    float s  = v.x + v.y + v.z + v.w;
    float ss = v.x*v.x + v.y*v.y + v.z*v.z + v.w*v.w;
    #pragma unroll
    for (int o = 16; o; o >>= 1) {
        s  += __shfl_xor_sync(0xffffffffu, s,  o);
        ss += __shfl_xor_sync(0xffffffffu, ss, o);
    }
    __shared__ float rs[8], rss[8];
    if ((t & 31) == 0) { rs[t >> 5] = s; rss[t >> 5] = ss; }
    __syncthreads();
    float S = 0.f, SS = 0.f;
    #pragma unroll
    for (int i = 0; i < 8; i++) { S += rs[i]; SS += rss[i]; }
    float mu = S * (1.f / IN_DIM);
    float var = SS * (1.f / IN_DIM) - mu * mu;
    float rstd = rsqrtf(var + 1e-5f);
    float4 wv = ((const float4*)w)[t];
    float4 bv = ((const float4*)b)[t];
    float o0 = (v.x - mu) * rstd * wv.x + bv.x;
    float o1 = (v.y - mu) * rstd * wv.y + bv.y;
    float o2 = (v.z - mu) * rstd * wv.z + bv.z;
    float o3 = (v.w - mu) * rstd * wv.w + bv.w;
    __nv_bfloat16 h0,l0,h1,l1,h2,l2,h3,l3;
    split_bf16(o0,h0,l0); split_bf16(o1,h1,l1);
    split_bf16(o2,h2,l2); split_bf16(o3,h3,l3);
    size_t base = (size_t)row * IN_DIM;
    ((__nv_bfloat162*)(hhi + base))[2*t]   = __nv_bfloat162(h0, h1);
    ((__nv_bfloat162*)(hhi + base))[2*t+1] = __nv_bfloat162(h2, h3);
    ((__nv_bfloat162*)(hlo + base))[2*t]   = __nv_bfloat162(l0, l1);
    ((__nv_bfloat162*)(hlo + base))[2*t+1] = __nv_bfloat162(l2, l3);
}

// ---------------- split tensor-core GEMM (ldmatrix, XOR-swizzle, 3-stage) ----------------
// F16=false: bf16 3-term (hh + lh + hl).  F16=true: f16 2-term (hh + lh), Bl unused.
#define KT  32
#define ARR_U32 (128 * 16)           // 2048 u32 = 8KB per array
#define STAGE_U32 (4 * ARR_U32)      // 32KB per stage
#define GEMM_SMEM_BYTES (3 * STAGE_U32 * 4)   // 98304

template<bool F16>
__global__ __launch_bounds__(256, 2) void gemm_split(
    const uint16_t* __restrict__ Ah, const uint16_t* __restrict__ Al,
    const uint16_t* __restrict__ Bh, const uint16_t* __restrict__ Bl,
    const float* __restrict__ Res, float* __restrict__ C,
    int N, int K)
{
    extern __shared__ __align__(16) uint32_t dsm[];

    const int tid  = threadIdx.x;
    const int warp = tid >> 5;
    const int lane = tid & 31;
    const int gid  = lane >> 2;
    const int tig  = lane & 3;
    const int wm   = warp & 1;
    const int wn   = warp >> 1;
    const int row0 = blockIdx.y * 128;
    const int col0 = blockIdx.x * 128;

    float acc[4][4][4];
    #pragma unroll
    for (int i = 0; i < 4; i++)
        #pragma unroll
        for (int j = 0; j < 4; j++)
            #pragma unroll
            for (int k = 0; k < 4; k++) acc[i][j][k] = 0.f;

    const int nk = K / KT;
    const uint32_t smem0 = (uint32_t)__cvta_generic_to_shared(dsm);

    auto load_stage = [&](int kt) {
        const int k0 = kt * KT;
        uint32_t* sb = dsm + (kt % 3) * STAGE_U32;
        #pragma unroll
        for (int half = 0; half < 2; half++) {
            int c2 = tid + half * 256;
            int r = c2 >> 2, f = c2 & 3;
            int fs = f ^ ((r >> 1) & 3);
            size_t aoff = (size_t)(row0 + r) * K + k0 + f * 8;
            size_t boff = (size_t)(col0 + r) * K + k0 + f * 8;
            uint32_t* dst = sb + r * 16 + fs * 4;
            cp_async16(dst,               Ah + aoff);
            cp_async16(dst + ARR_U32,     Al + aoff);
            cp_async16(dst + 2 * ARR_U32, Bh + boff);
            if (!F16) cp_async16(dst + 3 * ARR_U32, Bl + boff);
        }
        asm volatile("cp.async.commit_group;\n" ::);
    };

    load_stage(0);
    load_stage(1);

    const int a_sub = lane >> 3;
    const int a_rin = lane & 7;
    const int a_row0 = wm * 64 + (a_sub & 1) * 8 + a_rin;
    const int a_ph  = (a_row0 >> 1) & 3;
    const uint32_t a_byte0 = (uint32_t)(a_row0 * 64);
    const uint32_t a_ch[2] = { (uint32_t)((((a_sub >> 1)    ) ^ a_ph) * 16),
                               (uint32_t)(((2 + (a_sub >> 1)) ^ a_ph) * 16) };
    const int b_row0 = wn * 32 + (lane & 7);
    const int b_ph  = (b_row0 >> 1) & 3;
    const uint32_t b_byte0 = (uint32_t)(b_row0 * 64);
    const int b_sub = (lane >> 3) & 1;
    const uint32_t b_ch[2] = { (uint32_t)(((b_sub    ) ^ b_ph) * 16),
                               (uint32_t)(((2 + b_sub) ^ b_ph) * 16) };

    for (int kt = 0; kt < nk; kt++) {
        asm volatile("cp.async.wait_group 1;\n" ::);
        __syncthreads();
        if (kt + 2 < nk) load_stage(kt + 2);
        else asm volatile("cp.async.commit_group;\n" ::);

        const uint32_t sbase = smem0 + (uint32_t)((kt % 3) * STAGE_U32 * 4);
        const uint32_t sAh = sbase;
        const uint32_t sAl = sbase + ARR_U32 * 4;
        const uint32_t sBh = sbase + 2 * ARR_U32 * 4;
        const uint32_t sBl = sbase + 3 * ARR_U32 * 4;

        #pragma unroll
        for (int kb = 0; kb < 2; kb++) {
            uint32_t ah[4][4], al[4][4];
            #pragma unroll
            for (int mt = 0; mt < 4; mt++) {
                uint32_t off = a_byte0 + (uint32_t)(mt * 16 * 64) + a_ch[kb];
                ldsm_x4(ah[mt], sAh + off);
                ldsm_x4(al[mt], sAl + off);
            }
            uint32_t bh[4][2], bl[4][2];
            #pragma unroll
            for (int nt = 0; nt < 4; nt++) {
                uint32_t off = b_byte0 + (uint32_t)(nt * 8 * 64) + b_ch[kb];
                ldsm_x2(bh[nt], sBh + off);
                if (!F16) ldsm_x2(bl[nt], sBl + off);
            }
            #pragma unroll
            for (int nt = 0; nt < 4; nt++)
                #pragma unroll
                for (int mt = 0; mt < 4; mt++) {
                    if (F16) mma_f16(acc[mt][nt], ah[mt], bh[nt]);
                    else     mma_bf16(acc[mt][nt], ah[mt], bh[nt]);
                }
            #pragma unroll
            for (int nt = 0; nt < 4; nt++)
                #pragma unroll
                for (int mt = 0; mt < 4; mt++) {
                    if (F16) mma_f16(acc[mt][nt], al[mt], bh[nt]);
                    else     mma_bf16(acc[mt][nt], al[mt], bh[nt]);
                }
            if (!F16) {
                #pragma unroll
                for (int nt = 0; nt < 4; nt++)
                    #pragma unroll
                    for (int mt = 0; mt < 4; mt++) mma_bf16(acc[mt][nt], ah[mt], bl[nt]);
            }
        }
    }

    #pragma unroll
    for (int mt = 0; mt < 4; mt++) {
        #pragma unroll
        for (int nt = 0; nt < 4; nt++) {
            int r = row0 + wm * 64 + mt * 16 + gid;
            int c = col0 + wn * 32 + nt * 8 + 2 * tig;
            if (c < N) {
                size_t o0 = (size_t)r * N + c;
                size_t o1 = (size_t)(r + 8) * N + c;
                float2 v0 = make_float2(acc[mt][nt][0], acc[mt][nt][1]);
                float2 v1 = make_float2(acc[mt][nt][2], acc[mt][nt][3]);
                if (Res) {
                    float2 r0 = *(const float2*)&Res[o0];
                    float2 r1 = *(const float2*)&Res[o1];
                    v0.x += r0.x; v0.y += r0.y;
                    v1.x += r1.x; v1.y += r1.y;
                }
                *(float2*)&C[o0] = v0;
                *(float2*)&C[o1] = v1;
            }
        }
    }
}

// ---------------- transform: elu_p1+sum_norm on q,k; sigmoid beta; relayout ----------------
__global__ __launch_bounds__(256) void transform_kernel(
    const float* __restrict__ qkvb,
    float* __restrict__ Q, float* __restrict__ Kk,
    float* __restrict__ V, float* __restrict__ Beta)
{
    int gw   = blockIdx.x * 8 + (threadIdx.x >> 5);
    int lane = threadIdx.x & 31;
    int h  = gw & 15;
    int tb = gw >> 4;
    int b  = tb & 7;
    int t  = tb >> 3;
    const float* src = qkvb + (size_t)tb * NOUT + h * (3*DH + 1);
    size_t dst = ((size_t)(b * NH + h) * SLEN + t) * DH;

    float q0 = elu_p1(src[lane]);
    float q1 = elu_p1(src[lane + 32]);
    float s = q0 + q1;
    #pragma unroll
    for (int o = 16; o; o >>= 1) s += __shfl_xor_sync(0xffffffffu, s, o);
    float inv = 1.f / s;
    Q[dst + lane]      = q0 * inv;
    Q[dst + lane + 32] = q1 * inv;

    float k0 = elu_p1(src[64 + lane]);
    float k1 = elu_p1(src[96 + lane]);
    s = k0 + k1;
    #pragma unroll
    for (int o = 16; o; o >>= 1) s += __shfl_xor_sync(0xffffffffu, s, o);
    inv = 1.f / s;
    Kk[dst + lane]      = k0 * inv;
    Kk[dst + lane + 32] = k1 * inv;

    V[dst + lane]      = src[128 + lane];
    V[dst + lane + 32] = src[160 + lane];

    if (lane == 0) {
        float x = src[192];
        Beta[(size_t)(b * NH + h) * SLEN + t] = 1.f / (1.f + __expf(-x));
    }
}

// ---------------- delta-rule scan v4: 2-step blocked + hoisted loads ----------------
// lane: row rloc = lane>>2 (8 rows), col group g = lane&3 (16 cols). W[16] regs.
#define CH 16
__global__ __launch_bounds__(32) void scan_kernel(
    const float* __restrict__ Q, const float* __restrict__ Kk,
    const float* __restrict__ V, const float* __restrict__ Beta,
    __half* __restrict__ Ohi, __half* __restrict__ Olo)
{
    __shared__ __align__(16) float sk[2][CH][64];
    __shared__ __align__(16) float sq[2][CH][64];
    __shared__ __align__(16) float sv[2][CH][8];
    __shared__ __align__(16) float sb[2][CH];

    const int bh = blockIdx.x >> 3;
    const int w  = blockIdx.x & 7;
    const int b = bh >> 4, h = bh & 15;
    const float* Kp = Kk   + (size_t)bh * SLEN * DH;
    const float* Vp = V    + (size_t)bh * SLEN * DH;
    const float* Qp = Q    + (size_t)bh * SLEN * DH;
    const float* Bp = Beta + (size_t)bh * SLEN;
    const int lane = threadIdx.x;
    const int rloc = lane >> 2;
    const int g = lane & 3;

    float W[16];
    #pragma unroll
    for (int m = 0; m < 16; m++) W[m] = 0.f;

    auto issue = [&](int c) {
        int buf = c & 1;
        int t0 = c * CH;
        #pragma unroll
        for (int j = 0; j < 8; j++) {
            int idx = lane + j * 32;
            int tt = idx >> 4, f = idx & 15;
            cp_async16(&sk[buf][tt][f * 4], Kp + (size_t)(t0 + tt) * DH + f * 4);
        }
        #pragma unroll
        for (int j = 0; j < 8; j++) {
            int idx = lane + j * 32;
            int tt = idx >> 4, f = idx & 15;
            cp_async16(&sq[buf][tt][f * 4], Qp + (size_t)(t0 + tt) * DH + f * 4);
        }
        {
            int tt = lane >> 1, hf = lane & 1;
            cp_async16(&sv[buf][tt][hf * 4], Vp + (size_t)(t0 + tt) * DH + w * 8 + hf * 4);
        }
        if (lane < 4) cp_async16(&sb[buf][lane * 4], Bp + t0 + lane * 4);
        asm volatile("cp.async.commit_group;\n" ::);
    };

    issue(0); issue(1);

    const int NC = SLEN / CH;
    const size_t obase = (size_t)b * IN_DIM + h * DH + w * 8 + rloc;

    for (int c = 0; c < NC; c++) {
        asm volatile("cp.async.wait_group 1;\n" ::);
        __syncwarp();
        const int buf = c & 1;

        #pragma unroll 2
        for (int p = 0; p < CH / 2; p++) {
            const int t1 = 2 * p, t2 = 2 * p + 1;
            // ---- hoist ALL loads for the pair (k1,k2,q1,q2,v,beta) up front ----
            float k1[16], k2[16], q1v[16], q2v[16];
            #pragma unroll
            for (int m = 0; m < 4; m++) {
                float4 a4 = *(const float4*)&sk[buf][t1][g * 16 + m * 4];
                k1[m*4+0] = a4.x; k1[m*4+1] = a4.y; k1[m*4+2] = a4.z; k1[m*4+3] = a4.w;
                float4 b4 = *(const float4*)&sk[buf][t2][g * 16 + m * 4];
                k2[m*4+0] = b4.x; k2[m*4+1] = b4.y; k2[m*4+2] = b4.z; k2[m*4+3] = b4.w;
                float4 c4 = *(const float4*)&sq[buf][t1][g * 16 + m * 4];
                q1v[m*4+0] = c4.x; q1v[m*4+1] = c4.y; q1v[m*4+2] = c4.z; q1v[m*4+3] = c4.w;
                float4 d4 = *(const float4*)&sq[buf][t2][g * 16 + m * 4];
                q2v[m*4+0] = d4.x; q2v[m*4+1] = d4.y; q2v[m*4+2] = d4.z; q2v[m*4+3] = d4.w;
            }
            float v1 = sv[buf][t1][rloc];
            float v2 = sv[buf][t2][rloc];
            float b1 = sb[buf][t1];
            float b2 = sb[buf][t2];

            // three dots off the same W (+ scalar kk)
            float pk1a = 0.f, pk1b = 0.f, pk2a = 0.f, pk2b = 0.f, kka = 0.f, kkb = 0.f;
            #pragma unroll
            for (int m = 0; m < 8; m++) {
                pk1a = fmaf(W[m],     k1[m],     pk1a);
                pk1b = fmaf(W[m + 8], k1[m + 8], pk1b);
                pk2a = fmaf(W[m],     k2[m],     pk2a);
                pk2b = fmaf(W[m + 8], k2[m + 8], pk2b);
                kka  = fmaf(k1[m],     k2[m],     kka);
                kkb  = fmaf(k1[m + 8], k2[m + 8], kkb);
            }
            float pk1 = pk1a + pk1b;
            float pk2 = pk2a + pk2b;
            float kk  = kka + kkb;
            pk1 += __shfl_xor_sync(0xffffffffu, pk1, 1);
            pk2 += __shfl_xor_sync(0xffffffffu, pk2, 1);
            kk  += __shfl_xor_sync(0xffffffffu, kk,  1);
            pk1 += __shfl_xor_sync(0xffffffffu, pk1, 2);
            pk2 += __shfl_xor_sync(0xffffffffu, pk2, 2);
            kk  += __shfl_xor_sync(0xffffffffu, kk,  2);

            float d1 = b1 * (v1 - pk1);
            float d2 = b2 * (v2 - pk2 - d1 * kk);

            // W += d1 k1; po1 = W . q1
            float po1a = 0.f, po1b = 0.f;
            #pragma unroll
            for (int m = 0; m < 8; m++) {
                W[m]     = fmaf(d1, k1[m],     W[m]);
                po1a     = fmaf(W[m],  q1v[m], po1a);
                W[m + 8] = fmaf(d1, k1[m + 8], W[m + 8]);
                po1b     = fmaf(W[m + 8], q1v[m + 8], po1b);
            }
            // W += d2 k2; po2 = W . q2
            float po2a = 0.f, po2b = 0.f;
            #pragma unroll
            for (int m = 0; m < 8; m++) {
                W[m]     = fmaf(d2, k2[m],     W[m]);
                po2a     = fmaf(W[m],  q2v[m], po2a);
                W[m + 8] = fmaf(d2, k2[m + 8], W[m + 8]);
                po2b     = fmaf(W[m + 8], q2v[m + 8], po2b);
            }

            float po1 = po1a + po1b;
            float po2 = po2a + po2b;
            po1 += __shfl_xor_sync(0xffffffffu, po1, 1);
            po2 += __shfl_xor_sync(0xffffffffu, po2, 1);
            po1 += __shfl_xor_sync(0xffffffffu, po1, 2);
            po2 += __shfl_xor_sync(0xffffffffu, po2, 2);

            if (g == 0) {
                int tg1 = c * CH + t1;
                size_t off1 = (size_t)tg1 * (BSZ * IN_DIM) + obase;
                size_t off2 = off1 + (BSZ * IN_DIM);
                __half hi, lo;
                split_f16(po1, hi, lo);
                Ohi[off1] = hi; Olo[off1] = lo;
                split_f16(po2, hi, lo);
                Ohi[off2] = hi; Olo[off2] = lo;
            }
        }
        __syncwarp();
        if (c + 2 < NC) issue(c + 2);
        else asm volatile("cp.async.commit_group;\n" ::);
    }
}

// ---------------- launcher ----------------
extern "C" void kernel_launch(void* const* d_in, const int* in_sizes, int n_in,
                              void* d_out, int out_size)
{
    const float* x      = (const float*)d_in[0];
    const float* ln_w   = (const float*)d_in[1];
    const float* ln_b   = (const float*)d_in[2];
    const float* w_slow = (const float*)d_in[3];
    const float* w_out  = (const float*)d_in[4];
    float* out = (float*)d_out;

    float *p_qkvb, *p_q, *p_k, *p_v, *p_beta;
    __nv_bfloat16 *p_h_hi, *p_h_lo, *p_ws_hi, *p_ws_lo;
    __half *p_o_hi, *p_o_lo, *p_wo_hi, *p_wo_lo;
    cudaGetSymbolAddress((void**)&p_qkvb, g_qkvb);
    cudaGetSymbolAddress((void**)&p_q,    g_q);
    cudaGetSymbolAddress((void**)&p_k,    g_k);
    cudaGetSymbolAddress((void**)&p_v,    g_v);
    cudaGetSymbolAddress((void**)&p_beta, g_beta);
    cudaGetSymbolAddress((void**)&p_h_hi, g_h_hi);
    cudaGetSymbolAddress((void**)&p_h_lo, g_h_lo);
    cudaGetSymbolAddress((void**)&p_o_hi, g_o_hi);
    cudaGetSymbolAddress((void**)&p_o_lo, g_o_lo);
    cudaGetSymbolAddress((void**)&p_ws_hi, g_ws_t_hi);
    cudaGetSymbolAddress((void**)&p_ws_lo, g_ws_t_lo);
    cudaGetSymbolAddress((void**)&p_wo_hi, g_wo_t_hi);
    cudaGetSymbolAddress((void**)&p_wo_lo, g_wo_t_lo);

    cudaFuncSetAttribute(gemm_split<false>, cudaFuncAttributeMaxDynamicSharedMemorySize,
                         GEMM_SMEM_BYTES);
    cudaFuncSetAttribute(gemm_split<true>, cudaFuncAttributeMaxDynamicSharedMemorySize,
                         GEMM_SMEM_BYTES);

    // 0. split+transpose weights
    {
        dim3 blk(32, 8);
        dim3 g1(NOUT_PAD / 32, IN_DIM / 32);
        split_transpose<<<g1, blk>>>(w_slow, p_ws_hi, p_ws_lo, IN_DIM, NOUT);
        dim3 g2(IN_DIM / 32, IN_DIM / 32);
        split_transpose_f16<<<g2, blk>>>(w_out, p_wo_hi, p_wo_lo, IN_DIM, IN_DIM);
    }

    // 1. LayerNorm -> split bf16
    ln_kernel<<<NROWS, 256>>>(x, ln_w, ln_b, p_h_hi, p_h_lo);

    // 2. qkvb = h @ w_slow   (bf16 3-term)
    {
        dim3 grid(NOUT_PAD / 128, NROWS / 128);
        gemm_split<false><<<grid, 256, GEMM_SMEM_BYTES>>>(
            (const uint16_t*)p_h_hi, (const uint16_t*)p_h_lo,
            (const uint16_t*)p_ws_hi, (const uint16_t*)p_ws_lo,
            nullptr, p_qkvb, NOUT, IN_DIM);
    }

    // 3. transform
    transform_kernel<<<(NROWS * NH) / 8, 256>>>(p_qkvb, p_q, p_k, p_v, p_beta);

    // 4. delta-rule scan (2-step blocked, hoisted loads, f16 output)
    scan_kernel<<<BSZ * NH * 8, 32>>>(p_q, p_k, p_v, p_beta, p_o_hi, p_o_lo);

    // 5. out = x + scan_out @ w_out   (f16 2-term)
    {
        dim3 grid(IN_DIM / 128, NROWS / 128);
        gemm_split<true><<<grid, 256, GEMM_SMEM_BYTES>>>(
            (const uint16_t*)p_o_hi, (const uint16_t*)p_o_lo,
            (const uint16_t*)p_wo_hi, (const uint16_t*)p_wo_lo,
            x, out, IN_DIM, IN_DIM);
    }
}

// round 12
// speedup vs baseline: 1.2547x; 1.1624x over previous
#include <cuda_runtime.h>
#include <cuda_bf16.h>
#include <cuda_fp16.h>
#include <cstdint>

// Problem constants
#define SLEN   2048
#define BSZ    8
#define IN_DIM 1024
#define NH     16
#define DH     64
#define NROWS  (SLEN*BSZ)              // 16384
#define NOUT   (NH*(3*DH+1))           // 3088
#define NOUT_PAD 3200

// ---------------- device scratch ----------------
__device__ __half g_h_hi[(size_t)NROWS * IN_DIM];      // f16 split LN output
__device__ __half g_h_lo[(size_t)NROWS * IN_DIM];
__device__ float g_qkvb[(size_t)NROWS * NOUT];
__device__ float g_q[(size_t)BSZ*NH*SLEN*DH];
__device__ float g_k[(size_t)BSZ*NH*SLEN*DH];
__device__ float g_v[(size_t)BSZ*NH*SLEN*DH];
__device__ float g_beta[(size_t)BSZ*NH*SLEN];
__device__ __half g_o_hi[(size_t)NROWS * IN_DIM];
__device__ __half g_o_lo[(size_t)NROWS * IN_DIM];
__device__ __half g_ws_t_hi[(size_t)NOUT_PAD * IN_DIM];
__device__ __half g_ws_t_lo[(size_t)NOUT_PAD * IN_DIM];
__device__ __half g_wo_t_hi[(size_t)IN_DIM * IN_DIM];
__device__ __half g_wo_t_lo[(size_t)IN_DIM * IN_DIM];

// ---------------- helpers ----------------
__device__ __forceinline__ void cp_async16(void* smem_dst, const void* gsrc) {
    unsigned s = (unsigned)__cvta_generic_to_shared(smem_dst);
    asm volatile("cp.async.cg.shared.global [%0], [%1], 16;\n" :: "r"(s), "l"(gsrc));
}
__device__ __forceinline__ float elu_p1(float x) {
    return x > 0.f ? x + 1.f : __expf(x);
}
__device__ __forceinline__ void split_f16(float x, __half& hi, __half& lo) {
    hi = __float2half(x);
    lo = __float2half(x - __half2float(hi));
}
__device__ __forceinline__ void mma_f16(float* d, const uint32_t* a, const uint32_t* b) {
    asm volatile("mma.sync.aligned.m16n8k16.row.col.f32.f16.f16.f32 "
        "{%0,%1,%2,%3}, {%4,%5,%6,%7}, {%8,%9}, {%0,%1,%2,%3};"
        : "+f"(d[0]), "+f"(d[1]), "+f"(d[2]), "+f"(d[3])
        : "r"(a[0]), "r"(a[1]), "r"(a[2]), "r"(a[3]), "r"(b[0]), "r"(b[1]));
}
__device__ __forceinline__ void ldsm_x4(uint32_t* r, uint32_t saddr) {
    asm volatile("ldmatrix.sync.aligned.m8n8.x4.shared.b16 {%0,%1,%2,%3}, [%4];"
        : "=r"(r[0]), "=r"(r[1]), "=r"(r[2]), "=r"(r[3]) : "r"(saddr));
}
__device__ __forceinline__ void ldsm_x2(uint32_t* r, uint32_t saddr) {
    asm volatile("ldmatrix.sync.aligned.m8n8.x2.shared.b16 {%0,%1}, [%2];"
        : "=r"(r[0]), "=r"(r[1]) : "r"(saddr));
}

// ---------------- split+transpose weights (f16): W[K][N] -> T[Npad][K] ----------------
__global__ __launch_bounds__(256) void split_transpose_f16(
    const float* __restrict__ W, __half* __restrict__ Th,
    __half* __restrict__ Tl, int K, int N)
{
    __shared__ float tile[32][33];
    int n0 = blockIdx.x * 32, k0 = blockIdx.y * 32;
    int tx = threadIdx.x, ty = threadIdx.y;
    #pragma unroll
    for (int i = 0; i < 32; i += 8) {
        int k = k0 + ty + i, n = n0 + tx;
        tile[ty + i][tx] = (n < N) ? W[(size_t)k * N + n] : 0.f;
    }
    __syncthreads();
    #pragma unroll
    for (int i = 0; i < 32; i += 8) {
        int n = n0 + ty + i, k = k0 + tx;
        float v = tile[tx][ty + i];
        __half hi, lo;
        split_f16(v, hi, lo);
        Th[(size_t)n * K + k] = hi;
        Tl[(size_t)n * K + k] = lo;
    }
}

// ---------------- LayerNorm: one block per row; writes split f16 ----------------
__global__ __launch_bounds__(256) void ln_kernel(
    const float* __restrict__ x, const float* __restrict__ w,
    const float* __restrict__ b, __half* __restrict__ hhi,
    __half* __restrict__ hlo)
{
    int row = blockIdx.x;
    int t = threadIdx.x;
    const float4* xr = (const float4*)(x + (size_t)row * IN_DIM);
    float4 v = xr[t];
    float s  = v.x + v.y + v.z + v.w;
    float ss = v.x*v.x + v.y*v.y + v.z*v.z + v.w*v.w;
    #pragma unroll
    for (int o = 16; o; o >>= 1) {
        s  += __shfl_xor_sync(0xffffffffu, s,  o);
        ss += __shfl_xor_sync(0xffffffffu, ss, o);
    }
    __shared__ float rs[8], rss[8];
    if ((t & 31) == 0) { rs[t >> 5] = s; rss[t >> 5] = ss; }
    __syncthreads();
    float S = 0.f, SS = 0.f;
    #pragma unroll
    for (int i = 0; i < 8; i++) { S += rs[i]; SS += rss[i]; }
    float mu = S * (1.f / IN_DIM);
    float var = SS * (1.f / IN_DIM) - mu * mu;
    float rstd = rsqrtf(var + 1e-5f);
    float4 wv = ((const float4*)w)[t];
    float4 bv = ((const float4*)b)[t];
    float o0 = (v.x - mu) * rstd * wv.x + bv.x;
    float o1 = (v.y - mu) * rstd * wv.y + bv.y;
    float o2 = (v.z - mu) * rstd * wv.z + bv.z;
    float o3 = (v.w - mu) * rstd * wv.w + bv.w;
    __half h0,l0,h1,l1,h2,l2,h3,l3;
    split_f16(o0,h0,l0); split_f16(o1,h1,l1);
    split_f16(o2,h2,l2); split_f16(o3,h3,l3);
    size_t base = (size_t)row * IN_DIM;
    ((__half2*)(hhi + base))[2*t]   = __half2(h0, h1);
    ((__half2*)(hhi + base))[2*t+1] = __half2(h2, h3);
    ((__half2*)(hlo + base))[2*t]   = __half2(l0, l1);
    ((__half2*)(hlo + base))[2*t+1] = __half2(l2, l3);
}

// ---------------- f16 2-term tensor-core GEMM (ldmatrix, XOR-swizzle, 3-stage) ----------------
// C = A @ B^T (+Res), terms: Ah*Bh + Al*Bh.
#define KT  32
#define ARR_U32 (128 * 16)           // 2048 u32 = 8KB per array
#define STAGE_U32 (3 * ARR_U32)      // 24KB per stage (Ah, Al, Bh)
#define GEMM_SMEM_BYTES (3 * STAGE_U32 * 4)   // 73728

__global__ __launch_bounds__(256, 2) void gemm_f16x2(
    const __half* __restrict__ Ah, const __half* __restrict__ Al,
    const __half* __restrict__ Bh,
    const float* __restrict__ Res, float* __restrict__ C,
    int N, int K)
{
    extern __shared__ __align__(16) uint32_t dsm[];

    const int tid  = threadIdx.x;
    const int warp = tid >> 5;
    const int lane = tid & 31;
    const int gid  = lane >> 2;
    const int tig  = lane & 3;
    const int wm   = warp & 1;
    const int wn   = warp >> 1;
    const int row0 = blockIdx.y * 128;
    const int col0 = blockIdx.x * 128;

    float acc[4][4][4];
    #pragma unroll
    for (int i = 0; i < 4; i++)
        #pragma unroll
        for (int j = 0; j < 4; j++)
            #pragma unroll
            for (int k = 0; k < 4; k++) acc[i][j][k] = 0.f;

    const int nk = K / KT;
    const uint32_t smem0 = (uint32_t)__cvta_generic_to_shared(dsm);

    auto load_stage = [&](int kt) {
        const int k0 = kt * KT;
        uint32_t* sb = dsm + (kt % 3) * STAGE_U32;
        #pragma unroll
        for (int half = 0; half < 2; half++) {
            int c2 = tid + half * 256;
            int r = c2 >> 2, f = c2 & 3;
            int fs = f ^ ((r >> 1) & 3);
            size_t aoff = (size_t)(row0 + r) * K + k0 + f * 8;
            size_t boff = (size_t)(col0 + r) * K + k0 + f * 8;
            uint32_t* dst = sb + r * 16 + fs * 4;
            cp_async16(dst,               Ah + aoff);
            cp_async16(dst + ARR_U32,     Al + aoff);
            cp_async16(dst + 2 * ARR_U32, Bh + boff);
        }
        asm volatile("cp.async.commit_group;\n" ::);
    };

    load_stage(0);
    load_stage(1);

    const int a_sub = lane >> 3;
    const int a_rin = lane & 7;
    const int a_row0 = wm * 64 + (a_sub & 1) * 8 + a_rin;
    const int a_ph  = (a_row0 >> 1) & 3;
    const uint32_t a_byte0 = (uint32_t)(a_row0 * 64);
    const uint32_t a_ch[2] = { (uint32_t)((((a_sub >> 1)    ) ^ a_ph) * 16),
                               (uint32_t)(((2 + (a_sub >> 1)) ^ a_ph) * 16) };
    const int b_row0 = wn * 32 + (lane & 7);
    const int b_ph  = (b_row0 >> 1) & 3;
    const uint32_t b_byte0 = (uint32_t)(b_row0 * 64);
    const int b_sub = (lane >> 3) & 1;
    const uint32_t b_ch[2] = { (uint32_t)(((b_sub    ) ^ b_ph) * 16),
                               (uint32_t)(((2 + b_sub) ^ b_ph) * 16) };

    for (int kt = 0; kt < nk; kt++) {
        asm volatile("cp.async.wait_group 1;\n" ::);
        __syncthreads();
        if (kt + 2 < nk) load_stage(kt + 2);
        else asm volatile("cp.async.commit_group;\n" ::);

        const uint32_t sbase = smem0 + (uint32_t)((kt % 3) * STAGE_U32 * 4);
        const uint32_t sAh = sbase;
        const uint32_t sAl = sbase + ARR_U32 * 4;
        const uint32_t sBh = sbase + 2 * ARR_U32 * 4;

        #pragma unroll
        for (int kb = 0; kb < 2; kb++) {
            uint32_t ah[4][4], al[4][4];
            #pragma unroll
            for (int mt = 0; mt < 4; mt++) {
                uint32_t off = a_byte0 + (uint32_t)(mt * 16 * 64) + a_ch[kb];
                ldsm_x4(ah[mt], sAh + off);
                ldsm_x4(al[mt], sAl + off);
            }
            uint32_t bh[4][2];
            #pragma unroll
            for (int nt = 0; nt < 4; nt++) {
                uint32_t off = b_byte0 + (uint32_t)(nt * 8 * 64) + b_ch[kb];
                ldsm_x2(bh[nt], sBh + off);
            }
            #pragma unroll
            for (int nt = 0; nt < 4; nt++)
                #pragma unroll
                for (int mt = 0; mt < 4; mt++) mma_f16(acc[mt][nt], ah[mt], bh[nt]);
            #pragma unroll
            for (int nt = 0; nt < 4; nt++)
                #pragma unroll
                for (int mt = 0; mt < 4; mt++) mma_f16(acc[mt][nt], al[mt], bh[nt]);
        }
    }

    #pragma unroll
    for (int mt = 0; mt < 4; mt++) {
        #pragma unroll
        for (int nt = 0; nt < 4; nt++) {
            int r = row0 + wm * 64 + mt * 16 + gid;
            int c = col0 + wn * 32 + nt * 8 + 2 * tig;
            if (c < N) {
                size_t o0 = (size_t)r * N + c;
                size_t o1 = (size_t)(r + 8) * N + c;
                float2 v0 = make_float2(acc[mt][nt][0], acc[mt][nt][1]);
                float2 v1 = make_float2(acc[mt][nt][2], acc[mt][nt][3]);
                if (Res) {
                    float2 r0 = *(const float2*)&Res[o0];
                    float2 r1 = *(const float2*)&Res[o1];
                    v0.x += r0.x; v0.y += r0.y;
                    v1.x += r1.x; v1.y += r1.y;
                }
                *(float2*)&C[o0] = v0;
                *(float2*)&C[o1] = v1;
            }
        }
    }
}

// ---------------- transform: elu_p1+sum_norm on q,k; sigmoid beta; relayout ----------------
__global__ __launch_bounds__(256) void transform_kernel(
    const float* __restrict__ qkvb,
    float* __restrict__ Q, float* __restrict__ Kk,
    float* __restrict__ V, float* __restrict__ Beta)
{
    int gw   = blockIdx.x * 8 + (threadIdx.x >> 5);
    int lane = threadIdx.x & 31;
    int h  = gw & 15;
    int tb = gw >> 4;
    int b  = tb & 7;
    int t  = tb >> 3;
    const float* src = qkvb + (size_t)tb * NOUT + h * (3*DH + 1);
    size_t dst = ((size_t)(b * NH + h) * SLEN + t) * DH;

    float q0 = elu_p1(src[lane]);
    float q1 = elu_p1(src[lane + 32]);
    float s = q0 + q1;
    #pragma unroll
    for (int o = 16; o; o >>= 1) s += __shfl_xor_sync(0xffffffffu, s, o);
    float inv = 1.f / s;
    Q[dst + lane]      = q0 * inv;
    Q[dst + lane + 32] = q1 * inv;

    float k0 = elu_p1(src[64 + lane]);
    float k1 = elu_p1(src[96 + lane]);
    s = k0 + k1;
    #pragma unroll
    for (int o = 16; o; o >>= 1) s += __shfl_xor_sync(0xffffffffu, s, o);
    inv = 1.f / s;
    Kk[dst + lane]      = k0 * inv;
    Kk[dst + lane + 32] = k1 * inv;

    V[dst + lane]      = src[128 + lane];
    V[dst + lane + 32] = src[160 + lane];

    if (lane == 0) {
        float x = src[192];
        Beta[(size_t)(b * NH + h) * SLEN + t] = 1.f / (1.f + __expf(-x));
    }
}

// ---------------- delta-rule scan: 2-step blocked, one WARP per (head, octet) ----------------
#define CH 16
__global__ __launch_bounds__(32) void scan_kernel(
    const float* __restrict__ Q, const float* __restrict__ Kk,
    const float* __restrict__ V, const float* __restrict__ Beta,
    __half* __restrict__ Ohi, __half* __restrict__ Olo)
{
    __shared__ __align__(16) float sk[2][CH][64];
    __shared__ __align__(16) float sq[2][CH][64];
    __shared__ __align__(16) float sv[2][CH][8];
    __shared__ __align__(16) float sb[2][CH];

    const int bh = blockIdx.x >> 3;
    const int w  = blockIdx.x & 7;
    const int b = bh >> 4, h = bh & 15;
    const float* Kp = Kk   + (size_t)bh * SLEN * DH;
    const float* Vp = V    + (size_t)bh * SLEN * DH;
    const float* Qp = Q    + (size_t)bh * SLEN * DH;
    const float* Bp = Beta + (size_t)bh * SLEN;
    const int lane = threadIdx.x;
    const int rloc = lane >> 2;
    const int g = lane & 3;

    float W[16];
    #pragma unroll
    for (int m = 0; m < 16; m++) W[m] = 0.f;

    auto issue = [&](int c) {
        int buf = c & 1;
        int t0 = c * CH;
        #pragma unroll
        for (int j = 0; j < 8; j++) {
            int idx = lane + j * 32;
            int tt = idx >> 4, f = idx & 15;
            cp_async16(&sk[buf][tt][f * 4], Kp + (size_t)(t0 + tt) * DH + f * 4);
        }
        #pragma unroll
        for (int j = 0; j < 8; j++) {
            int idx = lane + j * 32;
            int tt = idx >> 4, f = idx & 15;
            cp_async16(&sq[buf][tt][f * 4], Qp + (size_t)(t0 + tt) * DH + f * 4);
        }
        {
            int tt = lane >> 1, hf = lane & 1;
            cp_async16(&sv[buf][tt][hf * 4], Vp + (size_t)(t0 + tt) * DH + w * 8 + hf * 4);
        }
        if (lane < 4) cp_async16(&sb[buf][lane * 4], Bp + t0 + lane * 4);
        asm volatile("cp.async.commit_group;\n" ::);
    };

    issue(0); issue(1);

    const int NC = SLEN / CH;
    const size_t obase = (size_t)b * IN_DIM + h * DH + w * 8 + rloc;

    for (int c = 0; c < NC; c++) {
        asm volatile("cp.async.wait_group 1;\n" ::);
        __syncwarp();
        const int buf = c & 1;

        #pragma unroll 2
        for (int p = 0; p < CH / 2; p++) {
            const int t1 = 2 * p, t2 = 2 * p + 1;
            float k1[16], k2[16], q1v[16], q2v[16];
            #pragma unroll
            for (int m = 0; m < 4; m++) {
                float4 a4 = *(const float4*)&sk[buf][t1][g * 16 + m * 4];
                k1[m*4+0] = a4.x; k1[m*4+1] = a4.y; k1[m*4+2] = a4.z; k1[m*4+3] = a4.w;
                float4 b4 = *(const float4*)&sk[buf][t2][g * 16 + m * 4];
                k2[m*4+0] = b4.x; k2[m*4+1] = b4.y; k2[m*4+2] = b4.z; k2[m*4+3] = b4.w;
                float4 c4 = *(const float4*)&sq[buf][t1][g * 16 + m * 4];
                q1v[m*4+0] = c4.x; q1v[m*4+1] = c4.y; q1v[m*4+2] = c4.z; q1v[m*4+3] = c4.w;
                float4 d4 = *(const float4*)&sq[buf][t2][g * 16 + m * 4];
                q2v[m*4+0] = d4.x; q2v[m*4+1] = d4.y; q2v[m*4+2] = d4.z; q2v[m*4+3] = d4.w;
            }
            float v1 = sv[buf][t1][rloc];
            float v2 = sv[buf][t2][rloc];
            float b1 = sb[buf][t1];
            float b2 = sb[buf][t2];

            float pk1a = 0.f, pk1b = 0.f, pk2a = 0.f, pk2b = 0.f, kka = 0.f, kkb = 0.f;
            #pragma unroll
            for (int m = 0; m < 8; m++) {
                pk1a = fmaf(W[m],     k1[m],     pk1a);
                pk1b = fmaf(W[m + 8], k1[m + 8], pk1b);
                pk2a = fmaf(W[m],     k2[m],     pk2a);
                pk2b = fmaf(W[m + 8], k2[m + 8], pk2b);
                kka  = fmaf(k1[m],     k2[m],     kka);
                kkb  = fmaf(k1[m + 8], k2[m + 8], kkb);
            }
            float pk1 = pk1a + pk1b;
            float pk2 = pk2a + pk2b;
            float kk  = kka + kkb;
            pk1 += __shfl_xor_sync(0xffffffffu, pk1, 1);
            pk2 += __shfl_xor_sync(0xffffffffu, pk2, 1);
            kk  += __shfl_xor_sync(0xffffffffu, kk,  1);
            pk1 += __shfl_xor_sync(0xffffffffu, pk1, 2);
            pk2 += __shfl_xor_sync(0xffffffffu, pk2, 2);
            kk  += __shfl_xor_sync(0xffffffffu, kk,  2);

            float d1 = b1 * (v1 - pk1);
            float d2 = b2 * (v2 - pk2 - d1 * kk);

            float po1a = 0.f, po1b = 0.f;
            #pragma unroll
            for (int m = 0; m < 8; m++) {
                W[m]     = fmaf(d1, k1[m],     W[m]);
                po1a     = fmaf(W[m],  q1v[m], po1a);
                W[m + 8] = fmaf(d1, k1[m + 8], W[m + 8]);
                po1b     = fmaf(W[m + 8], q1v[m + 8], po1b);
            }
            float po2a = 0.f, po2b = 0.f;
            #pragma unroll
            for (int m = 0; m < 8; m++) {
                W[m]     = fmaf(d2, k2[m],     W[m]);
                po2a     = fmaf(W[m],  q2v[m], po2a);
                W[m + 8] = fmaf(d2, k2[m + 8], W[m + 8]);
                po2b     = fmaf(W[m + 8], q2v[m + 8], po2b);
            }

            float po1 = po1a + po1b;
            float po2 = po2a + po2b;
            po1 += __shfl_xor_sync(0xffffffffu, po1, 1);
            po2 += __shfl_xor_sync(0xffffffffu, po2, 1);
            po1 += __shfl_xor_sync(0xffffffffu, po1, 2);
            po2 += __shfl_xor_sync(0xffffffffu, po2, 2);

            if (g == 0) {
                int tg1 = c * CH + t1;
                size_t off1 = (size_t)tg1 * (BSZ * IN_DIM) + obase;
                size_t off2 = off1 + (BSZ * IN_DIM);
                __half hi, lo;
                split_f16(po1, hi, lo);
                Ohi[off1] = hi; Olo[off1] = lo;
                split_f16(po2, hi, lo);
                Ohi[off2] = hi; Olo[off2] = lo;
            }
        }
        __syncwarp();
        if (c + 2 < NC) issue(c + 2);
        else asm volatile("cp.async.commit_group;\n" ::);
    }
}

// ---------------- launcher ----------------
extern "C" void kernel_launch(void* const* d_in, const int* in_sizes, int n_in,
                              void* d_out, int out_size)
{
    const float* x      = (const float*)d_in[0];
    const float* ln_w   = (const float*)d_in[1];
    const float* ln_b   = (const float*)d_in[2];
    const float* w_slow = (const float*)d_in[3];
    const float* w_out  = (const float*)d_in[4];
    float* out = (float*)d_out;

    float *p_qkvb, *p_q, *p_k, *p_v, *p_beta;
    __half *p_h_hi, *p_h_lo, *p_o_hi, *p_o_lo;
    __half *p_ws_hi, *p_ws_lo, *p_wo_hi, *p_wo_lo;
    cudaGetSymbolAddress((void**)&p_qkvb, g_qkvb);
    cudaGetSymbolAddress((void**)&p_q,    g_q);
    cudaGetSymbolAddress((void**)&p_k,    g_k);
    cudaGetSymbolAddress((void**)&p_v,    g_v);
    cudaGetSymbolAddress((void**)&p_beta, g_beta);
    cudaGetSymbolAddress((void**)&p_h_hi, g_h_hi);
    cudaGetSymbolAddress((void**)&p_h_lo, g_h_lo);
    cudaGetSymbolAddress((void**)&p_o_hi, g_o_hi);
    cudaGetSymbolAddress((void**)&p_o_lo, g_o_lo);
    cudaGetSymbolAddress((void**)&p_ws_hi, g_ws_t_hi);
    cudaGetSymbolAddress((void**)&p_ws_lo, g_ws_t_lo);
    cudaGetSymbolAddress((void**)&p_wo_hi, g_wo_t_hi);
    cudaGetSymbolAddress((void**)&p_wo_lo, g_wo_t_lo);

    cudaFuncSetAttribute(gemm_f16x2, cudaFuncAttributeMaxDynamicSharedMemorySize,
                         GEMM_SMEM_BYTES);

    // 0. split+transpose weights (f16)
    {
        dim3 blk(32, 8);
        dim3 g1(NOUT_PAD / 32, IN_DIM / 32);
        split_transpose_f16<<<g1, blk>>>(w_slow, p_ws_hi, p_ws_lo, IN_DIM, NOUT);
        dim3 g2(IN_DIM / 32, IN_DIM / 32);
        split_transpose_f16<<<g2, blk>>>(w_out, p_wo_hi, p_wo_lo, IN_DIM, IN_DIM);
    }

    // 1. LayerNorm -> split f16
    ln_kernel<<<NROWS, 256>>>(x, ln_w, ln_b, p_h_hi, p_h_lo);

    // 2. qkvb = h @ w_slow   (f16 2-term)
    {
        dim3 grid(NOUT_PAD / 128, NROWS / 128);
        gemm_f16x2<<<grid, 256, GEMM_SMEM_BYTES>>>(
            p_h_hi, p_h_lo, p_ws_hi, nullptr, p_qkvb, NOUT, IN_DIM);
    }

    // 3. transform
    transform_kernel<<<(NROWS * NH) / 8, 256>>>(p_qkvb, p_q, p_k, p_v, p_beta);

    // 4. delta-rule scan (2-step blocked)
    scan_kernel<<<BSZ * NH * 8, 32>>>(p_q, p_k, p_v, p_beta, p_o_hi, p_o_lo);

    // 5. out = x + scan_out @ w_out   (f16 2-term)
    {
        dim3 grid(IN_DIM / 128, NROWS / 128);
        gemm_f16x2<<<grid, 256, GEMM_SMEM_BYTES>>>(
            p_o_hi, p_o_lo, p_wo_hi, x, out, IN_DIM, IN_DIM);
    }
}

// round 13
// speedup vs baseline: 1.6921x; 1.3486x over previous
#include <cuda_runtime.h>
#include <cuda_fp16.h>
#include <cstdint>

// Problem constants
#define SLEN   2048
#define BSZ    8
#define IN_DIM 1024
#define NH     16
#define DH     64
#define NROWS  (SLEN*BSZ)              // 16384
#define NOUT   (NH*(3*DH+1))           // 3088
#define NOUT_PAD 3200

// ---------------- device scratch ----------------
__device__ __half g_h[(size_t)NROWS * IN_DIM];        // f16 LN output
__device__ float g_qkvb[(size_t)NROWS * NOUT];
__device__ float g_q[(size_t)BSZ*NH*SLEN*DH];
__device__ float g_k[(size_t)BSZ*NH*SLEN*DH];
__device__ float g_v[(size_t)BSZ*NH*SLEN*DH];
__device__ float g_beta[(size_t)BSZ*NH*SLEN];
__device__ __half g_o[(size_t)NROWS * IN_DIM];        // f16 scan output
__device__ __half g_ws_t[(size_t)NOUT_PAD * IN_DIM];  // f16 [n][k]
__device__ __half g_wo_t[(size_t)IN_DIM * IN_DIM];

// ---------------- helpers ----------------
__device__ __forceinline__ void cp_async16(void* smem_dst, const void* gsrc) {
    unsigned s = (unsigned)__cvta_generic_to_shared(smem_dst);
    asm volatile("cp.async.cg.shared.global [%0], [%1], 16;\n" :: "r"(s), "l"(gsrc));
}
__device__ __forceinline__ float elu_p1(float x) {
    return x > 0.f ? x + 1.f : __expf(x);
}
__device__ __forceinline__ void mma_f16(float* d, const uint32_t* a, const uint32_t* b) {
    asm volatile("mma.sync.aligned.m16n8k16.row.col.f32.f16.f16.f32 "
        "{%0,%1,%2,%3}, {%4,%5,%6,%7}, {%8,%9}, {%0,%1,%2,%3};"
        : "+f"(d[0]), "+f"(d[1]), "+f"(d[2]), "+f"(d[3])
        : "r"(a[0]), "r"(a[1]), "r"(a[2]), "r"(a[3]), "r"(b[0]), "r"(b[1]));
}
__device__ __forceinline__ void ldsm_x4(uint32_t* r, uint32_t saddr) {
    asm volatile("ldmatrix.sync.aligned.m8n8.x4.shared.b16 {%0,%1,%2,%3}, [%4];"
        : "=r"(r[0]), "=r"(r[1]), "=r"(r[2]), "=r"(r[3]) : "r"(saddr));
}
__device__ __forceinline__ void ldsm_x2(uint32_t* r, uint32_t saddr) {
    asm volatile("ldmatrix.sync.aligned.m8n8.x2.shared.b16 {%0,%1}, [%2];"
        : "=r"(r[0]), "=r"(r[1]) : "r"(saddr));
}

// ---------------- cast+transpose weights: W[K][N] f32 -> T[Npad][K] f16 ----------------
__global__ __launch_bounds__(256) void cast_transpose_f16(
    const float* __restrict__ W, __half* __restrict__ T, int K, int N)
{
    __shared__ float tile[32][33];
    int n0 = blockIdx.x * 32, k0 = blockIdx.y * 32;
    int tx = threadIdx.x, ty = threadIdx.y;
    #pragma unroll
    for (int i = 0; i < 32; i += 8) {
        int k = k0 + ty + i, n = n0 + tx;
        tile[ty + i][tx] = (n < N) ? W[(size_t)k * N + n] : 0.f;
    }
    __syncthreads();
    #pragma unroll
    for (int i = 0; i < 32; i += 8) {
        int n = n0 + ty + i, k = k0 + tx;
        T[(size_t)n * K + k] = __float2half(tile[tx][ty + i]);
    }
}

// ---------------- LayerNorm: one block per row; writes f16 ----------------
__global__ __launch_bounds__(256) void ln_kernel(
    const float* __restrict__ x, const float* __restrict__ w,
    const float* __restrict__ b, __half* __restrict__ hout)
{
    int row = blockIdx.x;
    int t = threadIdx.x;
    const float4* xr = (const float4*)(x + (size_t)row * IN_DIM);
    float4 v = xr[t];
    float s  = v.x + v.y + v.z + v.w;
    float ss = v.x*v.x + v.y*v.y + v.z*v.z + v.w*v.w;
    #pragma unroll
    for (int o = 16; o; o >>= 1) {
        s  += __shfl_xor_sync(0xffffffffu, s,  o);
        ss += __shfl_xor_sync(0xffffffffu, ss, o);
    }
    __shared__ float rs[8], rss[8];
    if ((t & 31) == 0) { rs[t >> 5] = s; rss[t >> 5] = ss; }
    __syncthreads();
    float S = 0.f, SS = 0.f;
    #pragma unroll
    for (int i = 0; i < 8; i++) { S += rs[i]; SS += rss[i]; }
    float mu = S * (1.f / IN_DIM);
    float var = SS * (1.f / IN_DIM) - mu * mu;
    float rstd = rsqrtf(var + 1e-5f);
    float4 wv = ((const float4*)w)[t];
    float4 bv = ((const float4*)b)[t];
    float o0 = (v.x - mu) * rstd * wv.x + bv.x;
    float o1 = (v.y - mu) * rstd * wv.y + bv.y;
    float o2 = (v.z - mu) * rstd * wv.z + bv.z;
    float o3 = (v.w - mu) * rstd * wv.w + bv.w;
    size_t base = (size_t)row * IN_DIM;
    ((__half2*)(hout + base))[2*t]   = __half2(__float2half(o0), __float2half(o1));
    ((__half2*)(hout + base))[2*t+1] = __half2(__float2half(o2), __float2half(o3));
}

// ---------------- f16 HGEMM (ldmatrix, 128B-row XOR-swizzle, 3-stage, KT=64) ----------------
// C = A[MxK] @ B^T (B stored [n][k]) (+Res). BM=BN=128, 8 warps (2x4), 2 CTAs/SM.
// smem array: 128 rows x 128B (32 u32/row), phys 16B-chunk = logical ^ (row & 7).
#define KT  64
#define ARR_U32 (128 * 32)           // 4096 u32 = 16KB per array
#define STAGE_U32 (2 * ARR_U32)      // 32KB per stage (A, B)
#define GEMM_SMEM_BYTES (3 * STAGE_U32 * 4)   // 98304

__global__ __launch_bounds__(256, 2) void gemm_f16(
    const __half* __restrict__ A, const __half* __restrict__ B,
    const float* __restrict__ Res, float* __restrict__ C,
    int N, int K)
{
    extern __shared__ __align__(16) uint32_t dsm[];

    const int tid  = threadIdx.x;
    const int warp = tid >> 5;
    const int lane = tid & 31;
    const int gid  = lane >> 2;
    const int tig  = lane & 3;
    const int wm   = warp & 1;
    const int wn   = warp >> 1;
    const int row0 = blockIdx.y * 128;
    const int col0 = blockIdx.x * 128;

    float acc[4][4][4];
    #pragma unroll
    for (int i = 0; i < 4; i++)
        #pragma unroll
        for (int j = 0; j < 4; j++)
            #pragma unroll
            for (int k = 0; k < 4; k++) acc[i][j][k] = 0.f;

    const int nk = K / KT;
    const uint32_t smem0 = (uint32_t)__cvta_generic_to_shared(dsm);

    auto load_stage = [&](int kt) {
        const int k0 = kt * KT;
        uint32_t* sb = dsm + (kt % 3) * STAGE_U32;
        #pragma unroll
        for (int it = 0; it < 4; it++) {
            int c = tid + it * 256;            // 0..1023 chunks per array
            int r = c >> 3, f = c & 7;
            int fs = f ^ (r & 7);
            uint32_t* dst = sb + r * 32 + fs * 4;
            cp_async16(dst,           A + (size_t)(row0 + r) * K + k0 + f * 8);
            cp_async16(dst + ARR_U32, B + (size_t)(col0 + r) * K + k0 + f * 8);
        }
        asm volatile("cp.async.commit_group;\n" ::);
    };

    load_stage(0);
    load_stage(1);

    // --- ldmatrix lane addressing (128B rows, phase = row & 7) ---
    // A x4: row = wm*64 + mt*16 + (sub&1)*8 + rin; phase = rin (strides mult of 8)
    const int a_sub = lane >> 3;
    const int a_rin = lane & 7;
    const int a_row0 = wm * 64 + (a_sub & 1) * 8 + a_rin;
    const uint32_t a_byte0 = (uint32_t)(a_row0 * 128);
    uint32_t a_ch[4];
    #pragma unroll
    for (int kb = 0; kb < 4; kb++)
        a_ch[kb] = (uint32_t)((((kb * 2) + (a_sub >> 1)) ^ a_rin) * 16);
    // B x2 (lanes 0..15): row = wn*32 + nt*8 + (lane&7); phase = lane&7
    const int b_row0 = wn * 32 + (lane & 7);
    const int b_sub = (lane >> 3) & 1;
    const uint32_t b_byte0 = (uint32_t)(b_row0 * 128);
    uint32_t b_ch[4];
    #pragma unroll
    for (int kb = 0; kb < 4; kb++)
        b_ch[kb] = (uint32_t)((((kb * 2) + b_sub) ^ (lane & 7)) * 16);

    for (int kt = 0; kt < nk; kt++) {
        asm volatile("cp.async.wait_group 1;\n" ::);
        __syncthreads();
        if (kt + 2 < nk) load_stage(kt + 2);
        else asm volatile("cp.async.commit_group;\n" ::);

        const uint32_t sbase = smem0 + (uint32_t)((kt % 3) * STAGE_U32 * 4);
        const uint32_t sA = sbase;
        const uint32_t sB = sbase + ARR_U32 * 4;

        #pragma unroll
        for (int kb = 0; kb < 4; kb++) {
            uint32_t af[4][4];
            #pragma unroll
            for (int mt = 0; mt < 4; mt++)
                ldsm_x4(af[mt], sA + a_byte0 + (uint32_t)(mt * 16 * 128) + a_ch[kb]);
            uint32_t bf[4][2];
            #pragma unroll
            for (int nt = 0; nt < 4; nt++)
                ldsm_x2(bf[nt], sB + b_byte0 + (uint32_t)(nt * 8 * 128) + b_ch[kb]);
            #pragma unroll
            for (int nt = 0; nt < 4; nt++)
                #pragma unroll
                for (int mt = 0; mt < 4; mt++) mma_f16(acc[mt][nt], af[mt], bf[nt]);
        }
    }

    #pragma unroll
    for (int mt = 0; mt < 4; mt++) {
        #pragma unroll
        for (int nt = 0; nt < 4; nt++) {
            int r = row0 + wm * 64 + mt * 16 + gid;
            int c = col0 + wn * 32 + nt * 8 + 2 * tig;
            if (c < N) {
                size_t o0 = (size_t)r * N + c;
                size_t o1 = (size_t)(r + 8) * N + c;
                float2 v0 = make_float2(acc[mt][nt][0], acc[mt][nt][1]);
                float2 v1 = make_float2(acc[mt][nt][2], acc[mt][nt][3]);
                if (Res) {
                    float2 r0 = *(const float2*)&Res[o0];
                    float2 r1 = *(const float2*)&Res[o1];
                    v0.x += r0.x; v0.y += r0.y;
                    v1.x += r1.x; v1.y += r1.y;
                }
                *(float2*)&C[o0] = v0;
                *(float2*)&C[o1] = v1;
            }
        }
    }
}

// ---------------- transform: elu_p1+sum_norm on q,k; sigmoid beta; relayout ----------------
__global__ __launch_bounds__(256) void transform_kernel(
    const float* __restrict__ qkvb,
    float* __restrict__ Q, float* __restrict__ Kk,
    float* __restrict__ V, float* __restrict__ Beta)
{
    int gw   = blockIdx.x * 8 + (threadIdx.x >> 5);
    int lane = threadIdx.x & 31;
    int h  = gw & 15;
    int tb = gw >> 4;
    int b  = tb & 7;
    int t  = tb >> 3;
    const float* src = qkvb + (size_t)tb * NOUT + h * (3*DH + 1);
    size_t dst = ((size_t)(b * NH + h) * SLEN + t) * DH;

    float q0 = elu_p1(src[lane]);
    float q1 = elu_p1(src[lane + 32]);
    float s = q0 + q1;
    #pragma unroll
    for (int o = 16; o; o >>= 1) s += __shfl_xor_sync(0xffffffffu, s, o);
    float inv = 1.f / s;
    Q[dst + lane]      = q0 * inv;
    Q[dst + lane + 32] = q1 * inv;

    float k0 = elu_p1(src[64 + lane]);
    float k1 = elu_p1(src[96 + lane]);
    s = k0 + k1;
    #pragma unroll
    for (int o = 16; o; o >>= 1) s += __shfl_xor_sync(0xffffffffu, s, o);
    inv = 1.f / s;
    Kk[dst + lane]      = k0 * inv;
    Kk[dst + lane + 32] = k1 * inv;

    V[dst + lane]      = src[128 + lane];
    V[dst + lane + 32] = src[160 + lane];

    if (lane == 0) {
        float x = src[192];
        Beta[(size_t)(b * NH + h) * SLEN + t] = 1.f / (1.f + __expf(-x));
    }
}

// ---------------- delta-rule scan: 2-step blocked, one WARP per (head, octet) ----------------
#define CH 16
__global__ __launch_bounds__(32) void scan_kernel(
    const float* __restrict__ Q, const float* __restrict__ Kk,
    const float* __restrict__ V, const float* __restrict__ Beta,
    __half* __restrict__ O)
{
    __shared__ __align__(16) float sk[2][CH][64];
    __shared__ __align__(16) float sq[2][CH][64];
    __shared__ __align__(16) float sv[2][CH][8];
    __shared__ __align__(16) float sb[2][CH];

    const int bh = blockIdx.x >> 3;
    const int w  = blockIdx.x & 7;
    const int b = bh >> 4, h = bh & 15;
    const float* Kp = Kk   + (size_t)bh * SLEN * DH;
    const float* Vp = V    + (size_t)bh * SLEN * DH;
    const float* Qp = Q    + (size_t)bh * SLEN * DH;
    const float* Bp = Beta + (size_t)bh * SLEN;
    const int lane = threadIdx.x;
    const int rloc = lane >> 2;
    const int g = lane & 3;

    float W[16];
    #pragma unroll
    for (int m = 0; m < 16; m++) W[m] = 0.f;

    auto issue = [&](int c) {
        int buf = c & 1;
        int t0 = c * CH;
        #pragma unroll
        for (int j = 0; j < 8; j++) {
            int idx = lane + j * 32;
            int tt = idx >> 4, f = idx & 15;
            cp_async16(&sk[buf][tt][f * 4], Kp + (size_t)(t0 + tt) * DH + f * 4);
        }
        #pragma unroll
        for (int j = 0; j < 8; j++) {
            int idx = lane + j * 32;
            int tt = idx >> 4, f = idx & 15;
            cp_async16(&sq[buf][tt][f * 4], Qp + (size_t)(t0 + tt) * DH + f * 4);
        }
        {
            int tt = lane >> 1, hf = lane & 1;
            cp_async16(&sv[buf][tt][hf * 4], Vp + (size_t)(t0 + tt) * DH + w * 8 + hf * 4);
        }
        if (lane < 4) cp_async16(&sb[buf][lane * 4], Bp + t0 + lane * 4);
        asm volatile("cp.async.commit_group;\n" ::);
    };

    issue(0); issue(1);

    const int NC = SLEN / CH;
    const size_t obase = (size_t)b * IN_DIM + h * DH + w * 8 + rloc;

    for (int c = 0; c < NC; c++) {
        asm volatile("cp.async.wait_group 1;\n" ::);
        __syncwarp();
        const int buf = c & 1;

        #pragma unroll 2
        for (int p = 0; p < CH / 2; p++) {
            const int t1 = 2 * p, t2 = 2 * p + 1;
            float k1[16], k2[16], q1v[16], q2v[16];
            #pragma unroll
            for (int m = 0; m < 4; m++) {
                float4 a4 = *(const float4*)&sk[buf][t1][g * 16 + m * 4];
                k1[m*4+0] = a4.x; k1[m*4+1] = a4.y; k1[m*4+2] = a4.z; k1[m*4+3] = a4.w;
                float4 b4 = *(const float4*)&sk[buf][t2][g * 16 + m * 4];
                k2[m*4+0] = b4.x; k2[m*4+1] = b4.y; k2[m*4+2] = b4.z; k2[m*4+3] = b4.w;
                float4 c4 = *(const float4*)&sq[buf][t1][g * 16 + m * 4];
                q1v[m*4+0] = c4.x; q1v[m*4+1] = c4.y; q1v[m*4+2] = c4.z; q1v[m*4+3] = c4.w;
                float4 d4 = *(const float4*)&sq[buf][t2][g * 16 + m * 4];
                q2v[m*4+0] = d4.x; q2v[m*4+1] = d4.y; q2v[m*4+2] = d4.z; q2v[m*4+3] = d4.w;
            }
            float v1 = sv[buf][t1][rloc];
            float v2 = sv[buf][t2][rloc];
            float b1 = sb[buf][t1];
            float b2 = sb[buf][t2];

            float pk1a = 0.f, pk1b = 0.f, pk2a = 0.f, pk2b = 0.f, kka = 0.f, kkb = 0.f;
            #pragma unroll
            for (int m = 0; m < 8; m++) {
                pk1a = fmaf(W[m],     k1[m],     pk1a);
                pk1b = fmaf(W[m + 8], k1[m + 8], pk1b);
                pk2a = fmaf(W[m],     k2[m],     pk2a);
                pk2b = fmaf(W[m + 8], k2[m + 8], pk2b);
                kka  = fmaf(k1[m],     k2[m],     kka);
                kkb  = fmaf(k1[m + 8], k2[m + 8], kkb);
            }
            float pk1 = pk1a + pk1b;
            float pk2 = pk2a + pk2b;
            float kk  = kka + kkb;
            pk1 += __shfl_xor_sync(0xffffffffu, pk1, 1);
            pk2 += __shfl_xor_sync(0xffffffffu, pk2, 1);
            kk  += __shfl_xor_sync(0xffffffffu, kk,  1);
            pk1 += __shfl_xor_sync(0xffffffffu, pk1, 2);
            pk2 += __shfl_xor_sync(0xffffffffu, pk2, 2);
            kk  += __shfl_xor_sync(0xffffffffu, kk,  2);

            float d1 = b1 * (v1 - pk1);
            float d2 = b2 * (v2 - pk2 - d1 * kk);

            float po1a = 0.f, po1b = 0.f;
            #pragma unroll
            for (int m = 0; m < 8; m++) {
                W[m]     = fmaf(d1, k1[m],     W[m]);
                po1a     = fmaf(W[m],  q1v[m], po1a);
                W[m + 8] = fmaf(d1, k1[m + 8], W[m + 8]);
                po1b     = fmaf(W[m + 8], q1v[m + 8], po1b);
            }
            float po2a = 0.f, po2b = 0.f;
            #pragma unroll
            for (int m = 0; m < 8; m++) {
                W[m]     = fmaf(d2, k2[m],     W[m]);
                po2a     = fmaf(W[m],  q2v[m], po2a);
                W[m + 8] = fmaf(d2, k2[m + 8], W[m + 8]);
                po2b     = fmaf(W[m + 8], q2v[m + 8], po2b);
            }

            float po1 = po1a + po1b;
            float po2 = po2a + po2b;
            po1 += __shfl_xor_sync(0xffffffffu, po1, 1);
            po2 += __shfl_xor_sync(0xffffffffu, po2, 1);
            po1 += __shfl_xor_sync(0xffffffffu, po1, 2);
            po2 += __shfl_xor_sync(0xffffffffu, po2, 2);

            if (g == 0) {
                int tg1 = c * CH + t1;
                size_t off1 = (size_t)tg1 * (BSZ * IN_DIM) + obase;
                O[off1] = __float2half(po1);
                O[off1 + (BSZ * IN_DIM)] = __float2half(po2);
            }
        }
        __syncwarp();
        if (c + 2 < NC) issue(c + 2);
        else asm volatile("cp.async.commit_group;\n" ::);
    }
}

// ---------------- launcher ----------------
extern "C" void kernel_launch(void* const* d_in, const int* in_sizes, int n_in,
                              void* d_out, int out_size)
{
    const float* x      = (const float*)d_in[0];
    const float* ln_w   = (const float*)d_in[1];
    const float* ln_b   = (const float*)d_in[2];
    const float* w_slow = (const float*)d_in[3];
    const float* w_out  = (const float*)d_in[4];
    float* out = (float*)d_out;

    float *p_qkvb, *p_q, *p_k, *p_v, *p_beta;
    __half *p_h, *p_o, *p_ws, *p_wo;
    cudaGetSymbolAddress((void**)&p_qkvb, g_qkvb);
    cudaGetSymbolAddress((void**)&p_q,    g_q);
    cudaGetSymbolAddress((void**)&p_k,    g_k);
    cudaGetSymbolAddress((void**)&p_v,    g_v);
    cudaGetSymbolAddress((void**)&p_beta, g_beta);
    cudaGetSymbolAddress((void**)&p_h,    g_h);
    cudaGetSymbolAddress((void**)&p_o,    g_o);
    cudaGetSymbolAddress((void**)&p_ws,   g_ws_t);
    cudaGetSymbolAddress((void**)&p_wo,   g_wo_t);

    cudaFuncSetAttribute(gemm_f16, cudaFuncAttributeMaxDynamicSharedMemorySize,
                         GEMM_SMEM_BYTES);

    // 0. cast+transpose weights (f16)
    {
        dim3 blk(32, 8);
        dim3 g1(NOUT_PAD / 32, IN_DIM / 32);
        cast_transpose_f16<<<g1, blk>>>(w_slow, p_ws, IN_DIM, NOUT);
        dim3 g2(IN_DIM / 32, IN_DIM / 32);
        cast_transpose_f16<<<g2, blk>>>(w_out, p_wo, IN_DIM, IN_DIM);
    }

    // 1. LayerNorm -> f16
    ln_kernel<<<NROWS, 256>>>(x, ln_w, ln_b, p_h);

    // 2. qkvb = h @ w_slow   (f16 HGEMM)
    {
        dim3 grid(NOUT_PAD / 128, NROWS / 128);
        gemm_f16<<<grid, 256, GEMM_SMEM_BYTES>>>(p_h, p_ws, nullptr, p_qkvb,
                                                 NOUT, IN_DIM);
    }

    // 3. transform
    transform_kernel<<<(NROWS * NH) / 8, 256>>>(p_qkvb, p_q, p_k, p_v, p_beta);

    // 4. delta-rule scan (2-step blocked)
    scan_kernel<<<BSZ * NH * 8, 32>>>(p_q, p_k, p_v, p_beta, p_o);

    // 5. out = x + scan_out @ w_out   (f16 HGEMM)
    {
        dim3 grid(IN_DIM / 128, NROWS / 128);
        gemm_f16<<<grid, 256, GEMM_SMEM_BYTES>>>(p_o, p_wo, x, out,
                                                 IN_DIM, IN_DIM);
    }
}

// round 14
// speedup vs baseline: 1.9082x; 1.1277x over previous
#include <cuda_runtime.h>
#include <cuda_fp16.h>
#include <cstdint>

// Problem constants
#define SLEN   2048
#define BSZ    8
#define IN_DIM 1024
#define NH     16
#define DH     64
#define NROWS  (SLEN*BSZ)              // 16384
#define NOUT   (NH*(3*DH+1))           // 3088
#define HPAD   194                     // padded head stride (3*DH+1=193 -> 194)
#define NOUT2  (NH*HPAD)               // 3104
#define NOUT_PAD 3200

// ---------------- device scratch ----------------
__device__ __half g_h[(size_t)NROWS * IN_DIM];        // f16 LN output
__device__ __half g_qkvb[(size_t)NROWS * NOUT2];      // f16 GEMM1 output (padded heads)
__device__ float g_q[(size_t)BSZ*NH*SLEN*DH];
__device__ float g_k[(size_t)BSZ*NH*SLEN*DH];
__device__ float g_v[(size_t)BSZ*NH*SLEN*DH];
__device__ float g_beta[(size_t)BSZ*NH*SLEN];
__device__ __half g_o[(size_t)NROWS * IN_DIM];        // f16 scan output
__device__ __half g_ws_t[(size_t)NOUT_PAD * IN_DIM];  // f16 [n'][k], head-padded
__device__ __half g_wo_t[(size_t)IN_DIM * IN_DIM];

// ---------------- helpers ----------------
__device__ __forceinline__ void cp_async16(void* smem_dst, const void* gsrc) {
    unsigned s = (unsigned)__cvta_generic_to_shared(smem_dst);
    asm volatile("cp.async.cg.shared.global [%0], [%1], 16;\n" :: "r"(s), "l"(gsrc));
}
__device__ __forceinline__ float elu_p1(float x) {
    return x > 0.f ? x + 1.f : __expf(x);
}
__device__ __forceinline__ void mma_f16(float* d, const uint32_t* a, const uint32_t* b) {
    asm volatile("mma.sync.aligned.m16n8k16.row.col.f32.f16.f16.f32 "
        "{%0,%1,%2,%3}, {%4,%5,%6,%7}, {%8,%9}, {%0,%1,%2,%3};"
        : "+f"(d[0]), "+f"(d[1]), "+f"(d[2]), "+f"(d[3])
        : "r"(a[0]), "r"(a[1]), "r"(a[2]), "r"(a[3]), "r"(b[0]), "r"(b[1]));
}
__device__ __forceinline__ void ldsm_x4(uint32_t* r, uint32_t saddr) {
    asm volatile("ldmatrix.sync.aligned.m8n8.x4.shared.b16 {%0,%1,%2,%3}, [%4];"
        : "=r"(r[0]), "=r"(r[1]), "=r"(r[2]), "=r"(r[3]) : "r"(saddr));
}
__device__ __forceinline__ void ldsm_x2(uint32_t* r, uint32_t saddr) {
    asm volatile("ldmatrix.sync.aligned.m8n8.x2.shared.b16 {%0,%1}, [%2];"
        : "=r"(r[0]), "=r"(r[1]) : "r"(saddr));
}

// ---------------- cast+transpose weights: W[K][N] f32 -> T[n'][K] f16 ----------------
// pad!=0: n' = n + n/193 (per-head padding 193->194)
__global__ __launch_bounds__(256) void cast_transpose_f16(
    const float* __restrict__ W, __half* __restrict__ T, int K, int N, int pad)
{
    __shared__ float tile[32][33];
    int n0 = blockIdx.x * 32, k0 = blockIdx.y * 32;
    int tx = threadIdx.x, ty = threadIdx.y;
    #pragma unroll
    for (int i = 0; i < 32; i += 8) {
        int k = k0 + ty + i, n = n0 + tx;
        tile[ty + i][tx] = (n < N) ? W[(size_t)k * N + n] : 0.f;
    }
    __syncthreads();
    #pragma unroll
    for (int i = 0; i < 32; i += 8) {
        int n = n0 + ty + i, k = k0 + tx;
        if (n < N) {
            int np = pad ? (n + n / 193) : n;
            T[(size_t)np * K + k] = __float2half(tile[tx][ty + i]);
        }
    }
}

// ---------------- LayerNorm: one block per row; writes f16 ----------------
__global__ __launch_bounds__(256) void ln_kernel(
    const float* __restrict__ x, const float* __restrict__ w,
    const float* __restrict__ b, __half* __restrict__ hout)
{
    int row = blockIdx.x;
    int t = threadIdx.x;
    const float4* xr = (const float4*)(x + (size_t)row * IN_DIM);
    float4 v = xr[t];
    float s  = v.x + v.y + v.z + v.w;
    float ss = v.x*v.x + v.y*v.y + v.z*v.z + v.w*v.w;
    #pragma unroll
    for (int o = 16; o; o >>= 1) {
        s  += __shfl_xor_sync(0xffffffffu, s,  o);
        ss += __shfl_xor_sync(0xffffffffu, ss, o);
    }
    __shared__ float rs[8], rss[8];
    if ((t & 31) == 0) { rs[t >> 5] = s; rss[t >> 5] = ss; }
    __syncthreads();
    float S = 0.f, SS = 0.f;
    #pragma unroll
    for (int i = 0; i < 8; i++) { S += rs[i]; SS += rss[i]; }
    float mu = S * (1.f / IN_DIM);
    float var = SS * (1.f / IN_DIM) - mu * mu;
    float rstd = rsqrtf(var + 1e-5f);
    float4 wv = ((const float4*)w)[t];
    float4 bv = ((const float4*)b)[t];
    float o0 = (v.x - mu) * rstd * wv.x + bv.x;
    float o1 = (v.y - mu) * rstd * wv.y + bv.y;
    float o2 = (v.z - mu) * rstd * wv.z + bv.z;
    float o3 = (v.w - mu) * rstd * wv.w + bv.w;
    size_t base = (size_t)row * IN_DIM;
    ((__half2*)(hout + base))[2*t]   = __half2(__float2half(o0), __float2half(o1));
    ((__half2*)(hout + base))[2*t+1] = __half2(__float2half(o2), __float2half(o3));
}

// ---------------- f16 HGEMM (ldmatrix, 128B-row XOR-swizzle, 3-stage, KT=64) ----------------
// HOUT=false: C float (+Res).  HOUT=true: C half, no Res.
#define KT  64
#define ARR_U32 (128 * 32)           // 4096 u32 = 16KB per array
#define STAGE_U32 (2 * ARR_U32)      // 32KB per stage (A, B)
#define GEMM_SMEM_BYTES (3 * STAGE_U32 * 4)   // 98304

template<bool HOUT>
__global__ __launch_bounds__(256, 2) void gemm_f16(
    const __half* __restrict__ A, const __half* __restrict__ B,
    const float* __restrict__ Res, void* __restrict__ Cv,
    int N, int K)
{
    extern __shared__ __align__(16) uint32_t dsm[];

    const int tid  = threadIdx.x;
    const int warp = tid >> 5;
    const int lane = tid & 31;
    const int gid  = lane >> 2;
    const int tig  = lane & 3;
    const int wm   = warp & 1;
    const int wn   = warp >> 1;
    const int row0 = blockIdx.y * 128;
    const int col0 = blockIdx.x * 128;

    float acc[4][4][4];
    #pragma unroll
    for (int i = 0; i < 4; i++)
        #pragma unroll
        for (int j = 0; j < 4; j++)
            #pragma unroll
            for (int k = 0; k < 4; k++) acc[i][j][k] = 0.f;

    const int nk = K / KT;
    const uint32_t smem0 = (uint32_t)__cvta_generic_to_shared(dsm);

    auto load_stage = [&](int kt) {
        const int k0 = kt * KT;
        uint32_t* sb = dsm + (kt % 3) * STAGE_U32;
        #pragma unroll
        for (int it = 0; it < 4; it++) {
            int c = tid + it * 256;
            int r = c >> 3, f = c & 7;
            int fs = f ^ (r & 7);
            uint32_t* dst = sb + r * 32 + fs * 4;
            cp_async16(dst,           A + (size_t)(row0 + r) * K + k0 + f * 8);
            cp_async16(dst + ARR_U32, B + (size_t)(col0 + r) * K + k0 + f * 8);
        }
        asm volatile("cp.async.commit_group;\n" ::);
    };

    load_stage(0);
    load_stage(1);

    const int a_sub = lane >> 3;
    const int a_rin = lane & 7;
    const int a_row0 = wm * 64 + (a_sub & 1) * 8 + a_rin;
    const uint32_t a_byte0 = (uint32_t)(a_row0 * 128);
    uint32_t a_ch[4];
    #pragma unroll
    for (int kb = 0; kb < 4; kb++)
        a_ch[kb] = (uint32_t)((((kb * 2) + (a_sub >> 1)) ^ a_rin) * 16);
    const int b_row0 = wn * 32 + (lane & 7);
    const int b_sub = (lane >> 3) & 1;
    const uint32_t b_byte0 = (uint32_t)(b_row0 * 128);
    uint32_t b_ch[4];
    #pragma unroll
    for (int kb = 0; kb < 4; kb++)
        b_ch[kb] = (uint32_t)((((kb * 2) + b_sub) ^ (lane & 7)) * 16);

    for (int kt = 0; kt < nk; kt++) {
        asm volatile("cp.async.wait_group 1;\n" ::);
        __syncthreads();
        if (kt + 2 < nk) load_stage(kt + 2);
        else asm volatile("cp.async.commit_group;\n" ::);

        const uint32_t sbase = smem0 + (uint32_t)((kt % 3) * STAGE_U32 * 4);
        const uint32_t sA = sbase;
        const uint32_t sB = sbase + ARR_U32 * 4;

        #pragma unroll
        for (int kb = 0; kb < 4; kb++) {
            uint32_t af[4][4];
            #pragma unroll
            for (int mt = 0; mt < 4; mt++)
                ldsm_x4(af[mt], sA + a_byte0 + (uint32_t)(mt * 16 * 128) + a_ch[kb]);
            uint32_t bf[4][2];
            #pragma unroll
            for (int nt = 0; nt < 4; nt++)
                ldsm_x2(bf[nt], sB + b_byte0 + (uint32_t)(nt * 8 * 128) + b_ch[kb]);
            #pragma unroll
            for (int nt = 0; nt < 4; nt++)
                #pragma unroll
                for (int mt = 0; mt < 4; mt++) mma_f16(acc[mt][nt], af[mt], bf[nt]);
        }
    }

    #pragma unroll
    for (int mt = 0; mt < 4; mt++) {
        #pragma unroll
        for (int nt = 0; nt < 4; nt++) {
            int r = row0 + wm * 64 + mt * 16 + gid;
            int c = col0 + wn * 32 + nt * 8 + 2 * tig;
            if (c < N) {
                size_t o0 = (size_t)r * N + c;
                size_t o1 = (size_t)(r + 8) * N + c;
                if (HOUT) {
                    __half* C = (__half*)Cv;
                    *(__half2*)&C[o0] = __half2(__float2half(acc[mt][nt][0]),
                                                __float2half(acc[mt][nt][1]));
                    *(__half2*)&C[o1] = __half2(__float2half(acc[mt][nt][2]),
                                                __float2half(acc[mt][nt][3]));
                } else {
                    float* C = (float*)Cv;
                    float2 v0 = make_float2(acc[mt][nt][0], acc[mt][nt][1]);
                    float2 v1 = make_float2(acc[mt][nt][2], acc[mt][nt][3]);
                    if (Res) {
                        float2 r0 = *(const float2*)&Res[o0];
                        float2 r1 = *(const float2*)&Res[o1];
                        v0.x += r0.x; v0.y += r0.y;
                        v1.x += r1.x; v1.y += r1.y;
                    }
                    *(float2*)&C[o0] = v0;
                    *(float2*)&C[o1] = v1;
                }
            }
        }
    }
}

// ---------------- transform: f16 qkvb (padded heads) -> q,k,v,beta ----------------
// one warp per (t,b,h); lane handles elements 2*lane, 2*lane+1 of each 64-vector
__global__ __launch_bounds__(256) void transform_kernel(
    const __half* __restrict__ qkvb,
    float* __restrict__ Q, float* __restrict__ Kk,
    float* __restrict__ V, float* __restrict__ Beta)
{
    int gw   = blockIdx.x * 8 + (threadIdx.x >> 5);
    int lane = threadIdx.x & 31;
    int h  = gw & 15;
    int tb = gw >> 4;
    int b  = tb & 7;
    int t  = tb >> 3;
    const __half2* src2 = (const __half2*)(qkvb + (size_t)tb * NOUT2 + h * HPAD);
    size_t dst = ((size_t)(b * NH + h) * SLEN + t) * DH;

    float2 qf = __half22float2(src2[lane]);
    float q0 = elu_p1(qf.x), q1 = elu_p1(qf.y);
    float s = q0 + q1;
    #pragma unroll
    for (int o = 16; o; o >>= 1) s += __shfl_xor_sync(0xffffffffu, s, o);
    float inv = 1.f / s;
    *(float2*)&Q[dst + 2*lane] = make_float2(q0 * inv, q1 * inv);

    float2 kf = __half22float2(src2[32 + lane]);
    float k0 = elu_p1(kf.x), k1 = elu_p1(kf.y);
    s = k0 + k1;
    #pragma unroll
    for (int o = 16; o; o >>= 1) s += __shfl_xor_sync(0xffffffffu, s, o);
    inv = 1.f / s;
    *(float2*)&Kk[dst + 2*lane] = make_float2(k0 * inv, k1 * inv);

    float2 vf = __half22float2(src2[64 + lane]);
    *(float2*)&V[dst + 2*lane] = vf;

    if (lane == 0) {
        float x = __half2float(((const __half*)src2)[192]);
        Beta[(size_t)(b * NH + h) * SLEN + t] = 1.f / (1.f + __expf(-x));
    }
}

// ---------------- delta-rule scan: 2-step blocked, chunk-transposed smem ----------------
// Logical 16B chunk c of each 64-float row stored at physical chunk (c&3)*4+(c>>2).
// Reader (thread col-group g, sub-chunk m) reads physical chunk m*4+g -> bytes
// m*64+g*16: 4 distinct bank-groups, conflict-free.
#define CH 16
__global__ __launch_bounds__(32) void scan_kernel(
    const float* __restrict__ Q, const float* __restrict__ Kk,
    const float* __restrict__ V, const float* __restrict__ Beta,
    __half* __restrict__ O)
{
    __shared__ __align__(16) float sk[2][CH][64];
    __shared__ __align__(16) float sq[2][CH][64];
    __shared__ __align__(16) float sv[2][CH][8];
    __shared__ __align__(16) float sb[2][CH];

    const int bh = blockIdx.x >> 3;
    const int w  = blockIdx.x & 7;
    const int b = bh >> 4, h = bh & 15;
    const float* Kp = Kk   + (size_t)bh * SLEN * DH;
    const float* Vp = V    + (size_t)bh * SLEN * DH;
    const float* Qp = Q    + (size_t)bh * SLEN * DH;
    const float* Bp = Beta + (size_t)bh * SLEN;
    const int lane = threadIdx.x;
    const int rloc = lane >> 2;
    const int g = lane & 3;

    float W[16];
    #pragma unroll
    for (int m = 0; m < 16; m++) W[m] = 0.f;

    auto issue = [&](int c) {
        int buf = c & 1;
        int t0 = c * CH;
        #pragma unroll
        for (int j = 0; j < 8; j++) {
            int idx = lane + j * 32;
            int tt = idx >> 4, f = idx & 15;
            int fp = (f & 3) * 4 + (f >> 2);             // chunk transpose
            cp_async16(&sk[buf][tt][fp * 4], Kp + (size_t)(t0 + tt) * DH + f * 4);
        }
        #pragma unroll
        for (int j = 0; j < 8; j++) {
            int idx = lane + j * 32;
            int tt = idx >> 4, f = idx & 15;
            int fp = (f & 3) * 4 + (f >> 2);
            cp_async16(&sq[buf][tt][fp * 4], Qp + (size_t)(t0 + tt) * DH + f * 4);
        }
        {
            int tt = lane >> 1, hf = lane & 1;
            cp_async16(&sv[buf][tt][hf * 4], Vp + (size_t)(t0 + tt) * DH + w * 8 + hf * 4);
        }
        if (lane < 4) cp_async16(&sb[buf][lane * 4], Bp + t0 + lane * 4);
        asm volatile("cp.async.commit_group;\n" ::);
    };

    issue(0); issue(1);

    const int NC = SLEN / CH;
    const size_t obase = (size_t)b * IN_DIM + h * DH + w * 8 + rloc;

    for (int c = 0; c < NC; c++) {
        asm volatile("cp.async.wait_group 1;\n" ::);
        __syncwarp();
        const int buf = c & 1;

        #pragma unroll 2
        for (int p = 0; p < CH / 2; p++) {
            const int t1 = 2 * p, t2 = 2 * p + 1;
            float k1[16], k2[16], q1v[16], q2v[16];
            #pragma unroll
            for (int m = 0; m < 4; m++) {
                // physical chunk m*4+g holds logical k[g*16+m*4 .. +3]
                float4 a4 = *(const float4*)&sk[buf][t1][m * 16 + g * 4];
                k1[m*4+0] = a4.x; k1[m*4+1] = a4.y; k1[m*4+2] = a4.z; k1[m*4+3] = a4.w;
                float4 b4 = *(const float4*)&sk[buf][t2][m * 16 + g * 4];
                k2[m*4+0] = b4.x; k2[m*4+1] = b4.y; k2[m*4+2] = b4.z; k2[m*4+3] = b4.w;
                float4 c4 = *(const float4*)&sq[buf][t1][m * 16 + g * 4];
                q1v[m*4+0] = c4.x; q1v[m*4+1] = c4.y; q1v[m*4+2] = c4.z; q1v[m*4+3] = c4.w;
                float4 d4 = *(const float4*)&sq[buf][t2][m * 16 + g * 4];
                q2v[m*4+0] = d4.x; q2v[m*4+1] = d4.y; q2v[m*4+2] = d4.z; q2v[m*4+3] = d4.w;
            }
            float v1 = sv[buf][t1][rloc];
            float v2 = sv[buf][t2][rloc];
            float b1 = sb[buf][t1];
            float b2 = sb[buf][t2];

            float pk1a = 0.f, pk1b = 0.f, pk2a = 0.f, pk2b = 0.f, kka = 0.f, kkb = 0.f;
            #pragma unroll
            for (int m = 0; m < 8; m++) {
                pk1a = fmaf(W[m],     k1[m],     pk1a);
                pk1b = fmaf(W[m + 8], k1[m + 8], pk1b);
                pk2a = fmaf(W[m],     k2[m],     pk2a);
                pk2b = fmaf(W[m + 8], k2[m + 8], pk2b);
                kka  = fmaf(k1[m],     k2[m],     kka);
                kkb  = fmaf(k1[m + 8], k2[m + 8], kkb);
            }
            float pk1 = pk1a + pk1b;
            float pk2 = pk2a + pk2b;
            float kk  = kka + kkb;
            pk1 += __shfl_xor_sync(0xffffffffu, pk1, 1);
            pk2 += __shfl_xor_sync(0xffffffffu, pk2, 1);
            kk  += __shfl_xor_sync(0xffffffffu, kk,  1);
            pk1 += __shfl_xor_sync(0xffffffffu, pk1, 2);
            pk2 += __shfl_xor_sync(0xffffffffu, pk2, 2);
            kk  += __shfl_xor_sync(0xffffffffu, kk,  2);

            float d1 = b1 * (v1 - pk1);
            float d2 = b2 * (v2 - pk2 - d1 * kk);

            float po1a = 0.f, po1b = 0.f;
            #pragma unroll
            for (int m = 0; m < 8; m++) {
                W[m]     = fmaf(d1, k1[m],     W[m]);
                po1a     = fmaf(W[m],  q1v[m], po1a);
                W[m + 8] = fmaf(d1, k1[m + 8], W[m + 8]);
                po1b     = fmaf(W[m + 8], q1v[m + 8], po1b);
            }
            float po2a = 0.f, po2b = 0.f;
            #pragma unroll
            for (int m = 0; m < 8; m++) {
                W[m]     = fmaf(d2, k2[m],     W[m]);
                po2a     = fmaf(W[m],  q2v[m], po2a);
                W[m + 8] = fmaf(d2, k2[m + 8], W[m + 8]);
                po2b     = fmaf(W[m + 8], q2v[m + 8], po2b);
            }

            float po1 = po1a + po1b;
            float po2 = po2a + po2b;
            po1 += __shfl_xor_sync(0xffffffffu, po1, 1);
            po2 += __shfl_xor_sync(0xffffffffu, po2, 1);
            po1 += __shfl_xor_sync(0xffffffffu, po1, 2);
            po2 += __shfl_xor_sync(0xffffffffu, po2, 2);

            if (g == 0) {
                int tg1 = c * CH + t1;
                size_t off1 = (size_t)tg1 * (BSZ * IN_DIM) + obase;
                O[off1] = __float2half(po1);
                O[off1 + (BSZ * IN_DIM)] = __float2half(po2);
            }
        }
        __syncwarp();
        if (c + 2 < NC) issue(c + 2);
        else asm volatile("cp.async.commit_group;\n" ::);
    }
}

// ---------------- launcher ----------------
extern "C" void kernel_launch(void* const* d_in, const int* in_sizes, int n_in,
                              void* d_out, int out_size)
{
    const float* x      = (const float*)d_in[0];
    const float* ln_w   = (const float*)d_in[1];
    const float* ln_b   = (const float*)d_in[2];
    const float* w_slow = (const float*)d_in[3];
    const float* w_out  = (const float*)d_in[4];
    float* out = (float*)d_out;

    float *p_q, *p_k, *p_v, *p_beta;
    __half *p_h, *p_qkvb, *p_o, *p_ws, *p_wo;
    cudaGetSymbolAddress((void**)&p_qkvb, g_qkvb);
    cudaGetSymbolAddress((void**)&p_q,    g_q);
    cudaGetSymbolAddress((void**)&p_k,    g_k);
    cudaGetSymbolAddress((void**)&p_v,    g_v);
    cudaGetSymbolAddress((void**)&p_beta, g_beta);
    cudaGetSymbolAddress((void**)&p_h,    g_h);
    cudaGetSymbolAddress((void**)&p_o,    g_o);
    cudaGetSymbolAddress((void**)&p_ws,   g_ws_t);
    cudaGetSymbolAddress((void**)&p_wo,   g_wo_t);

    cudaFuncSetAttribute(gemm_f16<true>, cudaFuncAttributeMaxDynamicSharedMemorySize,
                         GEMM_SMEM_BYTES);
    cudaFuncSetAttribute(gemm_f16<false>, cudaFuncAttributeMaxDynamicSharedMemorySize,
                         GEMM_SMEM_BYTES);

    // 0. cast+transpose weights (f16; w_slow head-padded 193->194)
    {
        dim3 blk(32, 8);
        dim3 g1((NOUT + 31) / 32, IN_DIM / 32);
        cast_transpose_f16<<<g1, blk>>>(w_slow, p_ws, IN_DIM, NOUT, 1);
        dim3 g2(IN_DIM / 32, IN_DIM / 32);
        cast_transpose_f16<<<g2, blk>>>(w_out, p_wo, IN_DIM, IN_DIM, 0);
    }

    // 1. LayerNorm -> f16
    ln_kernel<<<NROWS, 256>>>(x, ln_w, ln_b, p_h);

    // 2. qkvb(f16, padded) = h @ w_slow
    {
        dim3 grid(NOUT_PAD / 128, NROWS / 128);
        gemm_f16<true><<<grid, 256, GEMM_SMEM_BYTES>>>(p_h, p_ws, nullptr, p_qkvb,
                                                       NOUT2, IN_DIM);
    }

    // 3. transform (f16 in)
    transform_kernel<<<(NROWS * NH) / 8, 256>>>(p_qkvb, p_q, p_k, p_v, p_beta);

    // 4. delta-rule scan (2-step blocked, conflict-free smem)
    scan_kernel<<<BSZ * NH * 8, 32>>>(p_q, p_k, p_v, p_beta, p_o);

    // 5. out = x + scan_out @ w_out
    {
        dim3 grid(IN_DIM / 128, NROWS / 128);
        gemm_f16<false><<<grid, 256, GEMM_SMEM_BYTES>>>(p_o, p_wo, x, out,
                                                        IN_DIM, IN_DIM);
    }
}